// round 2
// baseline (speedup 1.0000x reference)
#include <cuda_runtime.h>
#include <math.h>

#define BB    64
#define PP    196
#define EE    2048
#define HH    512
#define EMBD  512
#define VSZ   10000
#define TCAP  50
#define TMAXX 49
#define BPP   (BB*PP)          // 12544
#define KIH   (EE+EMBD)        // 2560
#define KCAT  3072             // EE+EMBD+HH

#define PRED_SZ   ((size_t)BB*TCAP*VSZ)
#define ALPHA_OFF PRED_SZ
#define ALPHA_SZ  ((size_t)BB*TCAP*PP)
#define DEC_OFF   (ALPHA_OFF + ALPHA_SZ)

// ---------------- scratch ----------------
__device__ float g_xwx[(size_t)BPP*EE];
__device__ float g_fm  [BB*EE];
__device__ float g_h   [BB*HH];
__device__ float g_hwh [BB*EE];
__device__ float g_gate[BB*EE];
__device__ float g_lam [BB*PP];
__device__ float g_inp [BB*KCAT];
__device__ float g_gru [BB*2048];
__device__ int   g_dec [BB];
__device__ float g_part[(size_t)79*8*64*128];   // split-K partials
__device__ unsigned int g_cnt[80];              // zero-init; finisher resets
__device__ float g_Wcomb[4096*512];             // [Wh_w ; f_beta_w]
__device__ float g_bcomb[4096];
__device__ float g_Wg[(size_t)2048*KCAT];       // combined GRU weight
__device__ float g_bg[2048];

typedef unsigned long long u64;
union F2U { u64 u; float2 f; };

__device__ __forceinline__ void ffma2(u64 &d, u64 a, u64 b){
    asm("fma.rn.f32x2 %0, %1, %2, %0;" : "+l"(d) : "l"(a), "l"(b));
}
__device__ __forceinline__ float tanha(float x){
    float y; asm("tanh.approx.f32 %0, %1;" : "=f"(y) : "f"(x)); return y;
}
__device__ __forceinline__ float sigf(float x){ return 1.f/(1.f+expf(-x)); }
__device__ __forceinline__ float sigfast(float x){ return 1.f/(1.f+__expf(-x)); }

// ---------------- tiny kernels ----------------
__global__ void dec_kernel(const int* __restrict__ lengths, float* __restrict__ outp){
    int b = threadIdx.x;
    if (b < BB){ int d = lengths[b]-1; g_dec[b] = d; outp[DEC_OFF+b] = (float)d; }
}

__global__ __launch_bounds__(256) void mean_kernel(const float* __restrict__ feat){
    int b = blockIdx.y;
    int e = blockIdx.x*256 + threadIdx.x;
    const float* f = feat + (size_t)b*PP*EE + e;
    float s = 0.f;
    #pragma unroll 4
    for (int p = 0; p < PP; p++) s += f[(size_t)p*EE];
    g_fm[b*EE+e] = s * (1.f/(float)PP);
}

// build [Wh_w ; f_beta_w] (4096 x 512) + bias
__global__ __launch_bounds__(256) void build_wcomb(const float* __restrict__ Whw, const float* __restrict__ Whb,
                                                   const float* __restrict__ fbw, const float* __restrict__ fbb){
    int idx = blockIdx.x*256 + threadIdx.x;      // 4096*512
    int n = idx >> 9, k = idx & 511;
    g_Wcomb[idx] = (n < EE) ? Whw[n*HH+k] : fbw[(n-EE)*HH+k];
    if (k == 0) g_bcomb[n] = (n < EE) ? Whb[n] : fbb[n-EE];
}

// combined GRU weight (2048 x 3072):
// rows [0,1024): [gih_rz | ghh_rz], bias summed
// rows [1024,1536): [gih_n | 0]
// rows [1536,2048): [0 | ghh_n]
__global__ __launch_bounds__(256) void build_wg(const float* __restrict__ gihw, const float* __restrict__ gihb,
                                                const float* __restrict__ ghhw, const float* __restrict__ ghhb){
    size_t idx = (size_t)blockIdx.x*256 + threadIdx.x;    // 2048*3072
    int n = (int)(idx / KCAT), k = (int)(idx % KCAT);
    float v;
    if (n < 1024)       v = (k < KIH) ? gihw[(size_t)n*KIH+k] : ghhw[(size_t)n*HH + (k-KIH)];
    else if (n < 1536)  v = (k < KIH) ? gihw[(size_t)n*KIH+k] : 0.f;
    else                v = (k < KIH) ? 0.f : ghhw[(size_t)(n-512)*HH + (k-KIH)];
    g_Wg[idx] = v;
    if (k == 0){
        if (n < 1024)      g_bg[n] = gihb[n] + ghhb[n];
        else if (n < 1536) g_bg[n] = gihb[n];
        else               g_bg[n] = ghhb[n-512];
    }
}

// ---------------- big SGEMM with FFMA2: x_wx = features @ Wx_w^T + b ----------------
// 128x128 tile, BK=8, per-thread 8 rows x 8 cols (4 f32x2 pairs)
__global__ __launch_bounds__(256) void xwx_gemm(const float* __restrict__ A,
                                                const float* __restrict__ W,
                                                const float* __restrict__ bias){
    __shared__ __align__(16) float As2[8][256];   // duplicated pairs
    __shared__ __align__(16) float Bs [8][128];
    int tid = threadIdx.x;
    int m0 = blockIdx.y*128, n0 = blockIdx.x*128;
    int lr = tid >> 1, lk = (tid & 1)*4;
    int ty = tid >> 4, tx = tid & 15;
    int r0 = ty*8, c0 = tx*8;

    u64 acc[8][4];
    #pragma unroll
    for (int i=0;i<8;i++)
        #pragma unroll
        for (int j=0;j<4;j++) acc[i][j]=0ull;

    const float* Ap = A + (size_t)(m0+lr)*EE + lk;
    const float* Wp = W + (size_t)(n0+lr)*EE + lk;

    for (int k0 = 0; k0 < EE; k0 += 8){
        float4 av = *(const float4*)(Ap + k0);
        float4 wv = *(const float4*)(Wp + k0);
        *(float2*)&As2[lk+0][2*lr] = make_float2(av.x,av.x);
        *(float2*)&As2[lk+1][2*lr] = make_float2(av.y,av.y);
        *(float2*)&As2[lk+2][2*lr] = make_float2(av.z,av.z);
        *(float2*)&As2[lk+3][2*lr] = make_float2(av.w,av.w);
        Bs[lk+0][lr]=wv.x; Bs[lk+1][lr]=wv.y; Bs[lk+2][lr]=wv.z; Bs[lk+3][lr]=wv.w;
        __syncthreads();
        #pragma unroll
        for (int kk = 0; kk < 8; kk++){
            u64 a2[8];
            #pragma unroll
            for (int i=0;i<8;i++) a2[i] = ((const u64*)&As2[kk][0])[r0+i];
            u64 w2[4];
            #pragma unroll
            for (int j=0;j<4;j++) w2[j] = ((const u64*)&Bs[kk][c0])[j];
            #pragma unroll
            for (int i=0;i<8;i++)
                #pragma unroll
                for (int j=0;j<4;j++) ffma2(acc[i][j], a2[i], w2[j]);
        }
        __syncthreads();
    }
    #pragma unroll
    for (int i=0;i<8;i++){
        size_t m = m0 + r0 + i;
        #pragma unroll
        for (int j=0;j<4;j++){
            int n = n0 + c0 + 2*j;
            F2U u; u.u = acc[i][j];
            g_xwx[m*EE + n]   = u.f.x + bias[n];
            g_xwx[m*EE + n+1] = u.f.y + bias[n+1];
        }
    }
}

// ---------------- skinny GEMM (M=64) with FFMA2 + split-K ----------------
// tile 64 x 128, BK=16, 256 threads, per-thread 4 rows x 8 cols (4 pairs)
// a_id: 0=g_fm(2048) 1=g_h(512) 2=g_inp(3072)
// w_id: 0=ext 1=g_Wcomb 2=g_Wg ; bias likewise
// c_id: 0=g_h  1=dual hwh/gate  2=g_gru  3=masked preds
__global__ __launch_bounds__(256) void gemm64(int a_id, int w_id,
                                              const float* __restrict__ Wext,
                                              const float* __restrict__ Bext,
                                              int c_id, int N, int K,
                                              float* __restrict__ outp, int t){
    const float* A  = (a_id==0) ? g_fm : (a_id==1) ? g_h : g_inp;
    int lda         = (a_id==0) ? EE   : (a_id==1) ? HH  : KCAT;
    const float* W  = (w_id==0) ? Wext : (w_id==1) ? g_Wcomb : g_Wg;
    const float* Bv = (w_id==0) ? Bext : (w_id==1) ? g_bcomb : g_bg;

    __shared__ __align__(16) float As2[16][128];
    __shared__ __align__(16) float Ws [16][128];
    __shared__ unsigned int s_last;

    int tid = threadIdx.x;
    int n0 = blockIdx.x*128;
    int ksplit = gridDim.z;
    int kchunk = K / ksplit;
    int kbeg = blockIdx.z * kchunk;
    int ar = tid >> 2, ak = (tid & 3) << 2;
    int wr = tid >> 1, wk = (tid & 1) << 3;
    int ty = tid >> 4, tx = tid & 15;
    int r0 = ty*4, c0 = tx*8;

    u64 acc[4][4];
    #pragma unroll
    for (int i=0;i<4;i++)
        #pragma unroll
        for (int j=0;j<4;j++) acc[i][j]=0ull;

    bool wvalid = (n0 + wr) < N;
    const float* Wp = W + (size_t)(n0+wr)*K;

    for (int k0 = kbeg; k0 < kbeg + kchunk; k0 += 16){
        float4 av = *(const float4*)(A + (size_t)ar*lda + k0 + ak);
        float4 w1 = make_float4(0,0,0,0), w2v = make_float4(0,0,0,0);
        if (wvalid){
            w1  = *(const float4*)(Wp + k0 + wk);
            w2v = *(const float4*)(Wp + k0 + wk + 4);
        }
        *(float2*)&As2[ak+0][2*ar] = make_float2(av.x,av.x);
        *(float2*)&As2[ak+1][2*ar] = make_float2(av.y,av.y);
        *(float2*)&As2[ak+2][2*ar] = make_float2(av.z,av.z);
        *(float2*)&As2[ak+3][2*ar] = make_float2(av.w,av.w);
        Ws[wk+0][wr]=w1.x; Ws[wk+1][wr]=w1.y; Ws[wk+2][wr]=w1.z; Ws[wk+3][wr]=w1.w;
        Ws[wk+4][wr]=w2v.x; Ws[wk+5][wr]=w2v.y; Ws[wk+6][wr]=w2v.z; Ws[wk+7][wr]=w2v.w;
        __syncthreads();
        #pragma unroll
        for (int kk = 0; kk < 16; kk++){
            u64 a2[4], wreg[4];
            #pragma unroll
            for (int i=0;i<4;i++) a2[i] = ((const u64*)&As2[kk][0])[r0+i];
            #pragma unroll
            for (int j=0;j<4;j++) wreg[j] = ((const u64*)&Ws[kk][c0])[j];
            #pragma unroll
            for (int i=0;i<4;i++)
                #pragma unroll
                for (int j=0;j<4;j++) ffma2(acc[i][j], a2[i], wreg[j]);
        }
        __syncthreads();
    }

    if (ksplit > 1){
        float* pp = &g_part[((size_t)blockIdx.x*8 + blockIdx.z)*8192];
        #pragma unroll
        for (int i=0;i<4;i++)
            #pragma unroll
            for (int j=0;j<4;j++){
                F2U u; u.u = acc[i][j];
                *(float2*)&pp[(r0+i)*128 + c0 + 2*j] = u.f;
            }
        __threadfence();
        __syncthreads();
        if (tid == 0){
            unsigned int v = atomicAdd(&g_cnt[blockIdx.x], 1u);
            s_last = (v == (unsigned)(ksplit-1)) ? 1u : 0u;
        }
        __syncthreads();
        if (!s_last) return;
        __threadfence();
        #pragma unroll
        for (int i=0;i<4;i++)
            #pragma unroll
            for (int j=0;j<4;j++){
                float2 s = make_float2(0.f,0.f);
                for (int kz = 0; kz < ksplit; kz++){
                    float2 p = *(float2*)&g_part[((size_t)blockIdx.x*8 + kz)*8192 + (r0+i)*128 + c0 + 2*j];
                    s.x += p.x; s.y += p.y;
                }
                F2U u; u.f = s; acc[i][j] = u.u;
            }
        __syncthreads();
        if (tid == 0) g_cnt[blockIdx.x] = 0;
    }

    #pragma unroll
    for (int i=0;i<4;i++){
        int r = r0 + i;
        #pragma unroll
        for (int j=0;j<4;j++){
            F2U u; u.u = acc[i][j];
            #pragma unroll
            for (int q=0;q<2;q++){
                int n = n0 + c0 + 2*j + q;
                if (n >= N) continue;
                float v = (q ? u.f.y : u.f.x) + Bv[n];
                if (c_id == 0){
                    g_h[(size_t)r*HH + n] = v;
                } else if (c_id == 1){
                    if (n < EE) g_hwh[(size_t)r*EE + n] = v;
                    else        g_gate[(size_t)r*EE + (n-EE)] = sigfast(v);
                } else if (c_id == 2){
                    g_gru[(size_t)r*2048 + n] = v;
                } else {
                    if (g_dec[r] >= t)
                        outp[(size_t)r*TCAP*VSZ + (size_t)t*VSZ + n] = v;
                }
            }
        }
    }
}

// ---------------- attention logits (4 p per block, tanh.approx) ----------------
__global__ __launch_bounds__(256) void att_kernel(const float* __restrict__ Vw,
                                                  const float* __restrict__ Vb){
    int b = blockIdx.y, p0 = blockIdx.x*4;
    int tid = threadIdx.x;
    const float4* h = (const float4*)(g_hwh + (size_t)b*EE);
    const float4* v = (const float4*)Vw;
    const float4* x0 = (const float4*)(g_xwx + (size_t)(b*PP + p0)*EE);
    float s[4] = {0.f,0.f,0.f,0.f};
    for (int i = tid; i < EE/4; i += 256){
        float4 hv = h[i], vv = v[i];
        #pragma unroll
        for (int pp = 0; pp < 4; pp++){
            float4 xv = x0[(size_t)pp*(EE/4) + i];
            s[pp] += tanha(xv.x+hv.x)*vv.x + tanha(xv.y+hv.y)*vv.y
                   + tanha(xv.z+hv.z)*vv.z + tanha(xv.w+hv.w)*vv.w;
        }
    }
    #pragma unroll
    for (int pp = 0; pp < 4; pp++)
        #pragma unroll
        for (int o = 16; o > 0; o >>= 1) s[pp] += __shfl_xor_sync(0xffffffffu, s[pp], o);
    __shared__ float sh[4][8];
    if ((tid & 31) == 0)
        #pragma unroll
        for (int pp = 0; pp < 4; pp++) sh[pp][tid>>5] = s[pp];
    __syncthreads();
    if (tid < 4){
        float tt = 0.f;
        #pragma unroll
        for (int w2 = 0; w2 < 8; w2++) tt += sh[tid][w2];
        g_lam[b*PP + p0 + tid] = tt + Vb[0];
    }
}

// ---------------- fused softmax + z + gate + embed + h-concat ----------------
__global__ __launch_bounds__(256) void zbuild_kernel(const float* __restrict__ feat,
                                                     const int* __restrict__ caps,
                                                     const float* __restrict__ embw,
                                                     float* __restrict__ outp, int t){
    int b = blockIdx.y, tid = threadIdx.x;
    __shared__ float red[256];
    __shared__ float salpha[PP];
    float v = (tid < PP) ? g_lam[b*PP + tid] : -1e30f;
    red[tid] = v; __syncthreads();
    for (int s2 = 128; s2 > 0; s2 >>= 1){ if (tid < s2) red[tid] = fmaxf(red[tid], red[tid+s2]); __syncthreads(); }
    float mx = red[0]; __syncthreads();
    float e = (tid < PP) ? expf(v - mx) : 0.f;
    red[tid] = e; __syncthreads();
    for (int s2 = 128; s2 > 0; s2 >>= 1){ if (tid < s2) red[tid] += red[tid+s2]; __syncthreads(); }
    float inv = 1.f / red[0];
    if (tid < PP) salpha[tid] = e * inv;
    __syncthreads();

    if (blockIdx.x == 0 && tid < PP && g_dec[b] >= t)
        outp[ALPHA_OFF + (size_t)b*TCAP*PP + (size_t)t*PP + tid] = salpha[tid];

    int ecol = blockIdx.x*256 + tid;        // 0..3071
    if (ecol < EE){
        const float* f = feat + (size_t)b*PP*EE + ecol;
        float s = 0.f;
        #pragma unroll 4
        for (int p = 0; p < PP; p++) s = fmaf(salpha[p], f[(size_t)p*EE], s);
        g_inp[(size_t)b*KCAT + ecol] = g_gate[b*EE + ecol] * s;
    } else if (ecol < KIH){
        int tok = caps[b*TCAP + t];
        g_inp[(size_t)b*KCAT + ecol] = embw[(size_t)tok*EMBD + (ecol - EE)];
    } else {
        g_inp[(size_t)b*KCAT + ecol] = g_h[b*HH + (ecol - KIH)];
    }
}

// ---------------- GRU combine + masked h update (precise math) ----------------
__global__ __launch_bounds__(256) void gru_combine(int t){
    int idx = blockIdx.x*256 + threadIdx.x;   // 0..32767
    int b = idx >> 9, j = idx & 511;
    const float* G = g_gru + (size_t)b*2048;
    float r  = sigf(G[j]);
    float z  = sigf(G[512 + j]);
    float n  = tanhf(G[1024 + j] + r * G[1536 + j]);
    float h  = g_h[b*HH + j];
    float hnew = (1.f - z)*n + z*h;
    if (g_dec[b] >= t) g_h[b*HH + j] = hnew;
}

// ---------------- launch ----------------
extern "C" void kernel_launch(void* const* d_in, const int* in_sizes, int n_in,
                              void* d_out, int out_size){
    const float* features = (const float*)d_in[0];
    const int*   captions = (const int*)  d_in[1];
    const int*   lengths  = (const int*)  d_in[2];
    const float* Wx_w  = (const float*)d_in[3];
    const float* Wx_b  = (const float*)d_in[4];
    const float* Wh_w  = (const float*)d_in[5];
    const float* Wh_b  = (const float*)d_in[6];
    const float* V_w   = (const float*)d_in[7];
    const float* V_b   = (const float*)d_in[8];
    const float* ih_w  = (const float*)d_in[9];
    const float* ih_b  = (const float*)d_in[10];
    const float* fb_w  = (const float*)d_in[11];
    const float* fb_b  = (const float*)d_in[12];
    const float* emb_w = (const float*)d_in[13];
    const float* gih_w = (const float*)d_in[14];
    const float* gih_b = (const float*)d_in[15];
    const float* ghh_w = (const float*)d_in[16];
    const float* ghh_b = (const float*)d_in[17];
    const float* fc1_w = (const float*)d_in[18];
    const float* fc1_b = (const float*)d_in[19];
    float* out = (float*)d_out;

    cudaMemsetAsync(d_out, 0, (size_t)out_size * sizeof(float), 0);
    dec_kernel<<<1, 64>>>(lengths, out);
    mean_kernel<<<dim3(EE/256, BB), 256>>>(features);
    build_wcomb<<<(4096*512)/256, 256>>>(Wh_w, Wh_b, fb_w, fb_b);
    build_wg<<<(2048*KCAT)/256, 256>>>(gih_w, gih_b, ghh_w, ghh_b);
    // h0 = fm @ init_h_w^T + b : N=512, K=2048, split-K 8
    gemm64<<<dim3(4, 1, 8), 256>>>(0, 0, ih_w, ih_b, 0, HH, EE, out, 0);
    xwx_gemm<<<dim3(EE/128, BPP/128), 256>>>(features, Wx_w, Wx_b);

    for (int t = 0; t < TMAXX; t++){
        // hwh + gate combined: N=4096, K=512
        gemm64<<<dim3(32, 1, 2), 256>>>(1, 1, nullptr, nullptr, 1, 4096, HH, out, t);
        att_kernel<<<dim3(PP/4, BB), 256>>>(V_w, V_b);
        zbuild_kernel<<<dim3(KCAT/256, BB), 256>>>(features, captions, emb_w, out, t);
        // combined GRU GEMM: N=2048, K=3072
        gemm64<<<dim3(16, 1, 8), 256>>>(2, 2, nullptr, nullptr, 2, 2048, KCAT, out, t);
        gru_combine<<<(BB*HH)/256, 256>>>(t);
        // fc1: N=10000, K=512, masked store to preds
        gemm64<<<dim3(79, 1, 2), 256>>>(1, 0, fc1_w, fc1_b, 3, VSZ, HH, out, t);
    }
}

// round 3
// speedup vs baseline: 2.3404x; 2.3404x over previous
#include <cuda_runtime.h>
#include <math.h>

#define BB    64
#define PP    196
#define EE    2048
#define HH    512
#define EMBD  512
#define VSZ   10000
#define TCAP  50
#define TMAXX 49
#define BPP   (BB*PP)          // 12544
#define KIH   (EE+EMBD)        // 2560
#define KCAT  3072             // EE+EMBD+HH

#define PRED_SZ   ((size_t)BB*TCAP*VSZ)
#define ALPHA_OFF PRED_SZ
#define ALPHA_SZ  ((size_t)BB*TCAP*PP)
#define DEC_OFF   (ALPHA_OFF + ALPHA_SZ)

// ---------------- scratch ----------------
__device__ float g_xwx[(size_t)BPP*EE];
__device__ float g_fm  [BB*EE];
__device__ float g_h   [BB*HH];
__device__ float g_hwh [BB*EE];
__device__ float g_gate[BB*EE];
__device__ float g_lam [BB*PP];
__device__ float g_inp [BB*KCAT];
__device__ float g_gru [BB*2048];
__device__ int   g_dec [BB];
__device__ float g_part[(size_t)79*8*64*128];   // split-K partials
__device__ unsigned int g_cnt[80];              // zero-init; finisher resets
__device__ float g_Wcomb[4096*512];             // [Wh_w ; f_beta_w]
__device__ float g_bcomb[4096];
__device__ float g_Wg[(size_t)2048*KCAT];       // combined GRU weight
__device__ float g_bg[2048];

// ---------------- helpers ----------------
__device__ __forceinline__ unsigned tf32c(float x){
    unsigned r; asm("cvt.rna.tf32.f32 %0, %1;" : "=r"(r) : "f"(x)); return r;
}
__device__ __forceinline__ void mma8(float* c, unsigned a0,unsigned a1,unsigned a2,unsigned a3,
                                     unsigned b0,unsigned b1){
    asm volatile("mma.sync.aligned.m16n8k8.row.col.f32.tf32.tf32.f32 "
        "{%0,%1,%2,%3}, {%4,%5,%6,%7}, {%8,%9}, {%0,%1,%2,%3};"
        : "+f"(c[0]),"+f"(c[1]),"+f"(c[2]),"+f"(c[3])
        : "r"(a0),"r"(a1),"r"(a2),"r"(a3),"r"(b0),"r"(b1));
}
__device__ __forceinline__ float tanha(float x){
    float y; asm("tanh.approx.f32 %0, %1;" : "=f"(y) : "f"(x)); return y;
}
__device__ __forceinline__ float sigf(float x){ return 1.f/(1.f+expf(-x)); }
__device__ __forceinline__ float sigfast(float x){ return 1.f/(1.f+__expf(-x)); }

// ---------------- tiny kernels ----------------
__global__ void dec_kernel(const int* __restrict__ lengths, float* __restrict__ outp){
    int b = threadIdx.x;
    if (b < BB){ int d = lengths[b]-1; g_dec[b] = d; outp[DEC_OFF+b] = (float)d; }
}

__global__ __launch_bounds__(256) void mean_kernel(const float* __restrict__ feat){
    int b = blockIdx.y;
    int e = blockIdx.x*256 + threadIdx.x;
    const float* f = feat + (size_t)b*PP*EE + e;
    float s = 0.f;
    #pragma unroll 4
    for (int p = 0; p < PP; p++) s += f[(size_t)p*EE];
    g_fm[b*EE+e] = s * (1.f/(float)PP);
}

__global__ __launch_bounds__(256) void build_wcomb(const float* __restrict__ Whw, const float* __restrict__ Whb,
                                                   const float* __restrict__ fbw, const float* __restrict__ fbb){
    int idx = blockIdx.x*256 + threadIdx.x;      // 4096*512
    int n = idx >> 9, k = idx & 511;
    g_Wcomb[idx] = (n < EE) ? Whw[n*HH+k] : fbw[(n-EE)*HH+k];
    if (k == 0) g_bcomb[n] = (n < EE) ? Whb[n] : fbb[n-EE];
}

// combined GRU weight (2048 x 3072):
// rows [0,1024): [gih_rz | ghh_rz] bias summed; [1024,1536): [gih_n | 0]; [1536,2048): [0 | ghh_n]
__global__ __launch_bounds__(256) void build_wg(const float* __restrict__ gihw, const float* __restrict__ gihb,
                                                const float* __restrict__ ghhw, const float* __restrict__ ghhb){
    size_t idx = (size_t)blockIdx.x*256 + threadIdx.x;    // 2048*3072
    int n = (int)(idx / KCAT), k = (int)(idx % KCAT);
    float v;
    if (n < 1024)       v = (k < KIH) ? gihw[(size_t)n*KIH+k] : ghhw[(size_t)n*HH + (k-KIH)];
    else if (n < 1536)  v = (k < KIH) ? gihw[(size_t)n*KIH+k] : 0.f;
    else                v = (k < KIH) ? 0.f : ghhw[(size_t)(n-512)*HH + (k-KIH)];
    g_Wg[idx] = v;
    if (k == 0){
        if (n < 1024)      g_bg[n] = gihb[n] + ghhb[n];
        else if (n < 1536) g_bg[n] = gihb[n];
        else               g_bg[n] = ghhb[n-512];
    }
}

// ---------------- tensor-core GEMM: C(Mx N) = A(MxK,row) @ W(NxK,row)^T + bias ----------------
// block tile 64(m) x 128(n), k-step 16, 8 warps (2m x 4n), warp tile 32x32.
// prec=1: 3-term tf32 compensation (AhiWhi + AloWhi + AhiWlo).
// a_id: 0=g_fm 1=g_h 2=g_inp 3=Aext ; w_id: 0=Wext 1=g_Wcomb 2=g_Wg
// c_id: 0=g_h 1=hwh/gate dual 2=g_gru 3=masked preds 4=g_xwx
__global__ __launch_bounds__(256) void mm_tc(int a_id, const float* __restrict__ Aext, int lda,
                                             int w_id, const float* __restrict__ Wext,
                                             const float* __restrict__ Bext,
                                             int c_id, int N, int K, int prec,
                                             float* __restrict__ outp, int t){
    const float* A  = (a_id==0) ? g_fm : (a_id==1) ? g_h : (a_id==2) ? g_inp : Aext;
    const float* W  = (w_id==0) ? Wext : (w_id==1) ? g_Wcomb : g_Wg;
    const float* Bv = (w_id==0) ? Bext : (w_id==1) ? g_bcomb : g_bg;

    __shared__ unsigned As[2][64][17];
    __shared__ unsigned Ws[2][128][17];
    __shared__ unsigned s_last;

    int tid = threadIdx.x;
    int m0 = blockIdx.y*64;
    int n0 = blockIdx.x*128;
    int ksplit = gridDim.z;
    int kchunk = K / ksplit;
    int kbeg = blockIdx.z * kchunk, kend = kbeg + kchunk;

    int arow = tid >> 2, acol = (tid & 3) * 4;
    int brow = tid >> 1, bcol = (tid & 1) * 8;
    bool bok = (n0 + brow) < N;
    const float* Ap = A + (size_t)(m0+arow)*lda + acol;
    const float* Wp = W + (size_t)(n0+brow)*K + bcol;

    int w = tid >> 5, lane = tid & 31, g = lane >> 2, c = lane & 3;
    int wm = (w >> 2) * 32, wn = (w & 3) * 32;

    float acc[2][4][4];
    #pragma unroll
    for (int i=0;i<2;i++)
        #pragma unroll
        for (int j=0;j<4;j++)
            #pragma unroll
            for (int q=0;q<4;q++) acc[i][j][q] = 0.f;

    // prefetch regs
    float4 ra, rb0, rb1;
    ra = *(const float4*)(Ap + kbeg);
    if (bok){ rb0 = *(const float4*)(Wp + kbeg); rb1 = *(const float4*)(Wp + kbeg + 4); }
    else    { rb0 = make_float4(0,0,0,0); rb1 = rb0; }

    for (int k0 = kbeg; k0 < kend; k0 += 16){
        // stage current tile to smem (hi + optional lo)
        {
            float av[4] = {ra.x, ra.y, ra.z, ra.w};
            #pragma unroll
            for (int j=0;j<4;j++){
                unsigned hi = tf32c(av[j]);
                As[0][arow][acol+j] = hi;
                if (prec) As[1][arow][acol+j] = tf32c(av[j] - __uint_as_float(hi));
            }
            float bv[8] = {rb0.x,rb0.y,rb0.z,rb0.w, rb1.x,rb1.y,rb1.z,rb1.w};
            #pragma unroll
            for (int j=0;j<8;j++){
                unsigned hi = tf32c(bv[j]);
                Ws[0][brow][bcol+j] = hi;
                if (prec) Ws[1][brow][bcol+j] = tf32c(bv[j] - __uint_as_float(hi));
            }
        }
        __syncthreads();
        // prefetch next tile
        if (k0 + 16 < kend){
            ra = *(const float4*)(Ap + k0 + 16);
            if (bok){ rb0 = *(const float4*)(Wp + k0 + 16); rb1 = *(const float4*)(Wp + k0 + 20); }
        }
        // mma over the staged tile
        #pragma unroll
        for (int kq = 0; kq < 2; kq++){
            int k8 = kq*8;
            unsigned ah[2][4], bh[4][2];
            #pragma unroll
            for (int mt=0;mt<2;mt++){
                int rm = wm + mt*16;
                ah[mt][0] = As[0][rm+g  ][k8+c];
                ah[mt][1] = As[0][rm+g+8][k8+c];
                ah[mt][2] = As[0][rm+g  ][k8+c+4];
                ah[mt][3] = As[0][rm+g+8][k8+c+4];
            }
            #pragma unroll
            for (int nt=0;nt<4;nt++){
                int nb = wn + nt*8;
                bh[nt][0] = Ws[0][nb+g][k8+c];
                bh[nt][1] = Ws[0][nb+g][k8+c+4];
            }
            #pragma unroll
            for (int mt=0;mt<2;mt++)
                #pragma unroll
                for (int nt=0;nt<4;nt++)
                    mma8(acc[mt][nt], ah[mt][0],ah[mt][1],ah[mt][2],ah[mt][3], bh[nt][0],bh[nt][1]);
            if (prec){
                unsigned al[2][4], bl[4][2];
                #pragma unroll
                for (int mt=0;mt<2;mt++){
                    int rm = wm + mt*16;
                    al[mt][0] = As[1][rm+g  ][k8+c];
                    al[mt][1] = As[1][rm+g+8][k8+c];
                    al[mt][2] = As[1][rm+g  ][k8+c+4];
                    al[mt][3] = As[1][rm+g+8][k8+c+4];
                }
                #pragma unroll
                for (int nt=0;nt<4;nt++){
                    int nb = wn + nt*8;
                    bl[nt][0] = Ws[1][nb+g][k8+c];
                    bl[nt][1] = Ws[1][nb+g][k8+c+4];
                }
                #pragma unroll
                for (int mt=0;mt<2;mt++)
                    #pragma unroll
                    for (int nt=0;nt<4;nt++){
                        mma8(acc[mt][nt], al[mt][0],al[mt][1],al[mt][2],al[mt][3], bh[nt][0],bh[nt][1]);
                        mma8(acc[mt][nt], ah[mt][0],ah[mt][1],ah[mt][2],ah[mt][3], bl[nt][0],bl[nt][1]);
                    }
            }
        }
        __syncthreads();
    }

    // split-K reduction (deterministic finisher)
    if (ksplit > 1){
        float* pp = &g_part[((size_t)blockIdx.x*8 + blockIdx.z)*8192];
        #pragma unroll
        for (int mt=0;mt<2;mt++)
            #pragma unroll
            for (int nt=0;nt<4;nt++){
                int r1 = wm + mt*16 + g;
                int cc = wn + nt*8 + 2*c;
                pp[r1*128 + cc]     = acc[mt][nt][0];
                pp[r1*128 + cc+1]   = acc[mt][nt][1];
                pp[(r1+8)*128 + cc]   = acc[mt][nt][2];
                pp[(r1+8)*128 + cc+1] = acc[mt][nt][3];
            }
        __threadfence();
        __syncthreads();
        if (tid == 0){
            unsigned v = atomicAdd(&g_cnt[blockIdx.x], 1u);
            s_last = (v == (unsigned)(ksplit-1)) ? 1u : 0u;
        }
        __syncthreads();
        if (!s_last) return;
        __threadfence();
        #pragma unroll
        for (int mt=0;mt<2;mt++)
            #pragma unroll
            for (int nt=0;nt<4;nt++){
                int r1 = wm + mt*16 + g;
                int cc = wn + nt*8 + 2*c;
                float s0=0.f,s1=0.f,s2=0.f,s3=0.f;
                for (int kz = 0; kz < ksplit; kz++){
                    const float* q = &g_part[((size_t)blockIdx.x*8 + kz)*8192];
                    s0 += q[r1*128 + cc];     s1 += q[r1*128 + cc+1];
                    s2 += q[(r1+8)*128 + cc]; s3 += q[(r1+8)*128 + cc+1];
                }
                acc[mt][nt][0]=s0; acc[mt][nt][1]=s1; acc[mt][nt][2]=s2; acc[mt][nt][3]=s3;
            }
        __syncthreads();
        if (tid == 0) g_cnt[blockIdx.x] = 0;
    }

    // epilogue
    #pragma unroll
    for (int mt=0;mt<2;mt++)
        #pragma unroll
        for (int nt=0;nt<4;nt++)
            #pragma unroll
            for (int q=0;q<4;q++){
                int r = wm + mt*16 + g + ((q>=2)?8:0);          // local row (batch / m)
                int n = n0 + wn + nt*8 + 2*c + (q&1);           // global col
                if (n >= N) continue;
                float v = acc[mt][nt][q] + Bv[n];
                if (c_id == 0){
                    g_h[(size_t)r*HH + n] = v;
                } else if (c_id == 1){
                    if (n < EE) g_hwh[(size_t)r*EE + n] = v;
                    else        g_gate[(size_t)r*EE + (n-EE)] = sigfast(v);
                } else if (c_id == 2){
                    g_gru[(size_t)r*2048 + n] = v;
                } else if (c_id == 3){
                    if (g_dec[r] >= t)
                        outp[(size_t)r*TCAP*VSZ + (size_t)t*VSZ + n] = v;
                } else {
                    g_xwx[(size_t)(m0 + r)*EE + n] = v;
                }
            }
}

// ---------------- attention logits (4 p per block, tanh.approx) ----------------
__global__ __launch_bounds__(256) void att_kernel(const float* __restrict__ Vw,
                                                  const float* __restrict__ Vb){
    int b = blockIdx.y, p0 = blockIdx.x*4;
    int tid = threadIdx.x;
    const float4* h = (const float4*)(g_hwh + (size_t)b*EE);
    const float4* v = (const float4*)Vw;
    const float4* x0 = (const float4*)(g_xwx + (size_t)(b*PP + p0)*EE);
    float s[4] = {0.f,0.f,0.f,0.f};
    for (int i = tid; i < EE/4; i += 256){
        float4 hv = h[i], vv = v[i];
        #pragma unroll
        for (int pp = 0; pp < 4; pp++){
            float4 xv = x0[(size_t)pp*(EE/4) + i];
            s[pp] += tanha(xv.x+hv.x)*vv.x + tanha(xv.y+hv.y)*vv.y
                   + tanha(xv.z+hv.z)*vv.z + tanha(xv.w+hv.w)*vv.w;
        }
    }
    #pragma unroll
    for (int pp = 0; pp < 4; pp++)
        #pragma unroll
        for (int o = 16; o > 0; o >>= 1) s[pp] += __shfl_xor_sync(0xffffffffu, s[pp], o);
    __shared__ float sh[4][8];
    if ((tid & 31) == 0)
        #pragma unroll
        for (int pp = 0; pp < 4; pp++) sh[pp][tid>>5] = s[pp];
    __syncthreads();
    if (tid < 4){
        float tt = 0.f;
        #pragma unroll
        for (int w2 = 0; w2 < 8; w2++) tt += sh[tid][w2];
        g_lam[b*PP + p0 + tid] = tt + Vb[0];
    }
}

// ---------------- fused softmax + z + gate + embed + h-concat ----------------
__global__ __launch_bounds__(256) void zbuild_kernel(const float* __restrict__ feat,
                                                     const int* __restrict__ caps,
                                                     const float* __restrict__ embw,
                                                     float* __restrict__ outp, int t){
    int b = blockIdx.y, tid = threadIdx.x;
    __shared__ float red[256];
    __shared__ float salpha[PP];
    float v = (tid < PP) ? g_lam[b*PP + tid] : -1e30f;
    red[tid] = v; __syncthreads();
    for (int s2 = 128; s2 > 0; s2 >>= 1){ if (tid < s2) red[tid] = fmaxf(red[tid], red[tid+s2]); __syncthreads(); }
    float mx = red[0]; __syncthreads();
    float e = (tid < PP) ? expf(v - mx) : 0.f;
    red[tid] = e; __syncthreads();
    for (int s2 = 128; s2 > 0; s2 >>= 1){ if (tid < s2) red[tid] += red[tid+s2]; __syncthreads(); }
    float inv = 1.f / red[0];
    if (tid < PP) salpha[tid] = e * inv;
    __syncthreads();

    if (blockIdx.x == 0 && tid < PP && g_dec[b] >= t)
        outp[ALPHA_OFF + (size_t)b*TCAP*PP + (size_t)t*PP + tid] = salpha[tid];

    int ecol = blockIdx.x*256 + tid;        // 0..3071
    if (ecol < EE){
        const float* f = feat + (size_t)b*PP*EE + ecol;
        float s = 0.f;
        #pragma unroll 4
        for (int p = 0; p < PP; p++) s = fmaf(salpha[p], f[(size_t)p*EE], s);
        g_inp[(size_t)b*KCAT + ecol] = g_gate[b*EE + ecol] * s;
    } else if (ecol < KIH){
        int tok = caps[b*TCAP + t];
        g_inp[(size_t)b*KCAT + ecol] = embw[(size_t)tok*EMBD + (ecol - EE)];
    } else {
        g_inp[(size_t)b*KCAT + ecol] = g_h[b*HH + (ecol - KIH)];
    }
}

// ---------------- GRU combine + masked h update (precise math) ----------------
__global__ __launch_bounds__(256) void gru_combine(int t){
    int idx = blockIdx.x*256 + threadIdx.x;   // 0..32767
    int b = idx >> 9, j = idx & 511;
    const float* G = g_gru + (size_t)b*2048;
    float r  = sigf(G[j]);
    float z  = sigf(G[512 + j]);
    float n  = tanhf(G[1024 + j] + r * G[1536 + j]);
    float h  = g_h[b*HH + j];
    float hnew = (1.f - z)*n + z*h;
    if (g_dec[b] >= t) g_h[b*HH + j] = hnew;
}

// ---------------- launch ----------------
extern "C" void kernel_launch(void* const* d_in, const int* in_sizes, int n_in,
                              void* d_out, int out_size){
    const float* features = (const float*)d_in[0];
    const int*   captions = (const int*)  d_in[1];
    const int*   lengths  = (const int*)  d_in[2];
    const float* Wx_w  = (const float*)d_in[3];
    const float* Wx_b  = (const float*)d_in[4];
    const float* Wh_w  = (const float*)d_in[5];
    const float* Wh_b  = (const float*)d_in[6];
    const float* V_w   = (const float*)d_in[7];
    const float* V_b   = (const float*)d_in[8];
    const float* ih_w  = (const float*)d_in[9];
    const float* ih_b  = (const float*)d_in[10];
    const float* fb_w  = (const float*)d_in[11];
    const float* fb_b  = (const float*)d_in[12];
    const float* emb_w = (const float*)d_in[13];
    const float* gih_w = (const float*)d_in[14];
    const float* gih_b = (const float*)d_in[15];
    const float* ghh_w = (const float*)d_in[16];
    const float* ghh_b = (const float*)d_in[17];
    const float* fc1_w = (const float*)d_in[18];
    const float* fc1_b = (const float*)d_in[19];
    float* out = (float*)d_out;

    cudaMemsetAsync(d_out, 0, (size_t)out_size * sizeof(float), 0);
    dec_kernel<<<1, 64>>>(lengths, out);
    mean_kernel<<<dim3(EE/256, BB), 256>>>(features);
    build_wcomb<<<(4096*512)/256, 256>>>(Wh_w, Wh_b, fb_w, fb_b);
    build_wg<<<(2048*KCAT)/256, 256>>>(gih_w, gih_b, ghh_w, ghh_b);
    // h0 = fm @ init_h_w^T + b : N=512, K=2048, compensated, split-K 8
    mm_tc<<<dim3(4, 1, 8), 256>>>(0, nullptr, EE, 0, ih_w, ih_b, 0, HH, EE, 1, out, 0);
    // x_wx = features @ Wx_w^T + b : M=12544, N=2048, K=2048, single tf32
    mm_tc<<<dim3(EE/128, BPP/64, 1), 256>>>(3, features, EE, 0, Wx_w, Wx_b, 4, EE, EE, 0, out, 0);

    for (int t = 0; t < TMAXX; t++){
        // hwh + gate combined: N=4096, K=512, compensated
        mm_tc<<<dim3(32, 1, 4), 256>>>(1, nullptr, HH, 1, nullptr, nullptr, 1, 4096, HH, 1, out, t);
        att_kernel<<<dim3(PP/4, BB), 256>>>(V_w, V_b);
        zbuild_kernel<<<dim3(KCAT/256, BB), 256>>>(features, captions, emb_w, out, t);
        // combined GRU GEMM: N=2048, K=3072, compensated
        mm_tc<<<dim3(16, 1, 8), 256>>>(2, nullptr, KCAT, 2, nullptr, nullptr, 2, 2048, KCAT, 1, out, t);
        gru_combine<<<(BB*HH)/256, 256>>>(t);
        // fc1: N=10000, K=512, compensated, masked store to preds
        mm_tc<<<dim3(79, 1, 4), 256>>>(1, nullptr, HH, 0, fc1_w, fc1_b, 3, VSZ, HH, 1, out, t);
    }
}

// round 4
// speedup vs baseline: 2.6311x; 1.1242x over previous
#include <cuda_runtime.h>
#include <cuda_fp16.h>
#include <math.h>

#define BB    64
#define PP    196
#define EE    2048
#define HH    512
#define EMBD  512
#define VSZ   10000
#define TCAP  50
#define TMAXX 49
#define BPP   (BB*PP)          // 12544
#define KIH   (EE+EMBD)        // 2560
#define KCAT  3072             // EE+EMBD+HH

#define PRED_SZ   ((size_t)BB*TCAP*VSZ)
#define ALPHA_OFF PRED_SZ
#define ALPHA_SZ  ((size_t)BB*TCAP*PP)
#define DEC_OFF   (ALPHA_OFF + ALPHA_SZ)

// ---------------- scratch ----------------
__device__ __half g_xwx_h[(size_t)BPP*EE];      // fp16 attention projections (51MB)
__device__ __half g_hwh_h[BB*EE];
__device__ float g_fm  [BB*EE];
__device__ float g_h   [BB*HH];
__device__ float g_gate[BB*EE];
__device__ float g_lam [BB*PP];
__device__ float g_inp [BB*KCAT];
__device__ float g_gru [BB*2048];
__device__ int   g_dec [BB];
__device__ float g_part[(size_t)79*8*64*128];   // split-K partials
__device__ unsigned int g_cnt[80];              // zero-init; finisher resets
__device__ float g_Wcomb[4096*512];             // [Wh_w ; f_beta_w]
__device__ float g_bcomb[4096];
__device__ float g_Wg[(size_t)2048*KCAT];       // combined GRU weight
__device__ float g_bg[2048];

// ---------------- helpers ----------------
__device__ __forceinline__ unsigned tf32c(float x){
    unsigned r; asm("cvt.rna.tf32.f32 %0, %1;" : "=r"(r) : "f"(x)); return r;
}
__device__ __forceinline__ void mma8(float* c, unsigned a0,unsigned a1,unsigned a2,unsigned a3,
                                     unsigned b0,unsigned b1){
    asm volatile("mma.sync.aligned.m16n8k8.row.col.f32.tf32.tf32.f32 "
        "{%0,%1,%2,%3}, {%4,%5,%6,%7}, {%8,%9}, {%0,%1,%2,%3};"
        : "+f"(c[0]),"+f"(c[1]),"+f"(c[2]),"+f"(c[3])
        : "r"(a0),"r"(a1),"r"(a2),"r"(a3),"r"(b0),"r"(b1));
}
__device__ __forceinline__ unsigned hadd2u(unsigned a, unsigned b){
    unsigned r; asm("add.f16x2 %0,%1,%2;" : "=r"(r) : "r"(a), "r"(b)); return r;
}
__device__ __forceinline__ unsigned tanh2(unsigned x){
    unsigned r; asm("tanh.approx.f16x2 %0,%1;" : "=r"(r) : "r"(x)); return r;
}
__device__ __forceinline__ void cpa16(void* smem, const void* g){
    unsigned sa = (unsigned)__cvta_generic_to_shared(smem);
    asm volatile("cp.async.cg.shared.global [%0], [%1], 16;" :: "r"(sa), "l"(g));
}
__device__ __forceinline__ void cpcommit(){ asm volatile("cp.async.commit_group;"); }
__device__ __forceinline__ void cpwait1(){ asm volatile("cp.async.wait_group 1;"); }
__device__ __forceinline__ float sigf(float x){ return 1.f/(1.f+expf(-x)); }
__device__ __forceinline__ float sigfast(float x){ return 1.f/(1.f+__expf(-x)); }

// ---------------- tiny kernels ----------------
__global__ void dec_kernel(const int* __restrict__ lengths, float* __restrict__ outp){
    int b = threadIdx.x;
    if (b < BB){ int d = lengths[b]-1; g_dec[b] = d; outp[DEC_OFF+b] = (float)d; }
}

__global__ __launch_bounds__(256) void mean_kernel(const float* __restrict__ feat){
    int b = blockIdx.y;
    int e = blockIdx.x*256 + threadIdx.x;
    const float* f = feat + (size_t)b*PP*EE + e;
    float s = 0.f;
    #pragma unroll 4
    for (int p = 0; p < PP; p++) s += f[(size_t)p*EE];
    g_fm[b*EE+e] = s * (1.f/(float)PP);
}

__global__ __launch_bounds__(256) void build_wcomb(const float* __restrict__ Whw, const float* __restrict__ Whb,
                                                   const float* __restrict__ fbw, const float* __restrict__ fbb){
    int idx = blockIdx.x*256 + threadIdx.x;      // 4096*512
    int n = idx >> 9, k = idx & 511;
    g_Wcomb[idx] = (n < EE) ? Whw[n*HH+k] : fbw[(n-EE)*HH+k];
    if (k == 0) g_bcomb[n] = (n < EE) ? Whb[n] : fbb[n-EE];
}

// combined GRU weight (2048 x 3072)
__global__ __launch_bounds__(256) void build_wg(const float* __restrict__ gihw, const float* __restrict__ gihb,
                                                const float* __restrict__ ghhw, const float* __restrict__ ghhb){
    size_t idx = (size_t)blockIdx.x*256 + threadIdx.x;    // 2048*3072
    int n = (int)(idx / KCAT), k = (int)(idx % KCAT);
    float v;
    if (n < 1024)       v = (k < KIH) ? gihw[(size_t)n*KIH+k] : ghhw[(size_t)n*HH + (k-KIH)];
    else if (n < 1536)  v = (k < KIH) ? gihw[(size_t)n*KIH+k] : 0.f;
    else                v = (k < KIH) ? 0.f : ghhw[(size_t)(n-512)*HH + (k-KIH)];
    g_Wg[idx] = v;
    if (k == 0){
        if (n < 1024)      g_bg[n] = gihb[n] + ghhb[n];
        else if (n < 1536) g_bg[n] = gihb[n];
        else               g_bg[n] = ghhb[n-512];
    }
}

// ---------------- big tf32 GEMM with cp.async double buffering ----------------
// xwx = features(12544x2048) @ Wx_w(2048x2048)^T + bias -> fp16 out
// tile 128x128, BK=16, 256 threads, 8 warps as 2(m)x4(n), warp tile 64x32.
#define XS 20
__global__ __launch_bounds__(256) void xwx_tc(const float* __restrict__ A,
                                              const float* __restrict__ W,
                                              const float* __restrict__ bias){
    __shared__ float As[2][128*XS];
    __shared__ float Bs[2][128*XS];
    int tid = threadIdx.x;
    int m0 = blockIdx.y*128, n0 = blockIdx.x*128;

    int rc = tid >> 2, kc = (tid & 3) * 4;     // chunk row / k-offset
    const float* Ap = A + (size_t)(m0+rc)*EE + kc;
    const float* Wp = W + (size_t)(n0+rc)*EE + kc;

    int wq = tid >> 5, lane = tid & 31, g = lane >> 2, ct = lane & 3;
    int wm = (wq >> 2) * 64, wn = (wq & 3) * 32;

    float acc[4][4][4];
    #pragma unroll
    for (int i=0;i<4;i++)
        #pragma unroll
        for (int j=0;j<4;j++)
            #pragma unroll
            for (int q=0;q<4;q++) acc[i][j][q] = 0.f;

    // prologue: stage 0, stage 1
    #pragma unroll
    for (int s = 0; s < 2; s++){
        int k0 = s*16;
        cpa16(&As[s][rc*XS + kc],      Ap + k0);
        cpa16(&As[s][(rc+64)*XS + kc], Ap + (size_t)64*EE + k0);
        cpa16(&Bs[s][rc*XS + kc],      Wp + k0);
        cpa16(&Bs[s][(rc+64)*XS + kc], Wp + (size_t)64*EE + k0);
        cpcommit();
    }

    for (int k0 = 0; k0 < EE; k0 += 16){
        int s = (k0 >> 4) & 1;
        cpwait1();
        __syncthreads();
        const unsigned* Au = (const unsigned*)As[s];
        const unsigned* Bu = (const unsigned*)Bs[s];
        #pragma unroll
        for (int kq = 0; kq < 2; kq++){
            int k8 = kq*8;
            unsigned ah[4][4], bh[4][2];
            #pragma unroll
            for (int mt=0;mt<4;mt++){
                int rm = wm + mt*16;
                ah[mt][0] = Au[(rm+g  )*XS + k8+ct];
                ah[mt][1] = Au[(rm+g+8)*XS + k8+ct];
                ah[mt][2] = Au[(rm+g  )*XS + k8+ct+4];
                ah[mt][3] = Au[(rm+g+8)*XS + k8+ct+4];
            }
            #pragma unroll
            for (int nt=0;nt<4;nt++){
                int nb = wn + nt*8;
                bh[nt][0] = Bu[(nb+g)*XS + k8+ct];
                bh[nt][1] = Bu[(nb+g)*XS + k8+ct+4];
            }
            #pragma unroll
            for (int mt=0;mt<4;mt++)
                #pragma unroll
                for (int nt=0;nt<4;nt++)
                    mma8(acc[mt][nt], ah[mt][0],ah[mt][1],ah[mt][2],ah[mt][3], bh[nt][0],bh[nt][1]);
        }
        __syncthreads();
        if (k0 + 32 < EE){
            int kn = k0 + 32;
            cpa16(&As[s][rc*XS + kc],      Ap + kn);
            cpa16(&As[s][(rc+64)*XS + kc], Ap + (size_t)64*EE + kn);
            cpa16(&Bs[s][rc*XS + kc],      Wp + kn);
            cpa16(&Bs[s][(rc+64)*XS + kc], Wp + (size_t)64*EE + kn);
            cpcommit();
        }
    }

    #pragma unroll
    for (int mt=0;mt<4;mt++){
        #pragma unroll
        for (int nt=0;nt<4;nt++){
            int cn = n0 + wn + nt*8 + 2*ct;
            float b0 = bias[cn], b1 = bias[cn+1];
            size_t r1 = (size_t)(m0 + wm + mt*16 + g);
            __half2 h2a = __floats2half2_rn(acc[mt][nt][0] + b0, acc[mt][nt][1] + b1);
            __half2 h2b = __floats2half2_rn(acc[mt][nt][2] + b0, acc[mt][nt][3] + b1);
            *(__half2*)&g_xwx_h[r1*EE + cn]     = h2a;
            *(__half2*)&g_xwx_h[(r1+8)*EE + cn] = h2b;
        }
    }
}

// ---------------- skinny tensor-core GEMM (M=64), compensated tf32 ----------------
// c_id: 0=g_h 1=hwh(fp16)/gate dual 2=g_gru 3=masked preds
__global__ __launch_bounds__(256) void mm_tc(int a_id, int lda,
                                             int w_id, const float* __restrict__ Wext,
                                             const float* __restrict__ Bext,
                                             int c_id, int N, int K, int prec,
                                             float* __restrict__ outp, int t){
    const float* A  = (a_id==0) ? g_fm : (a_id==1) ? g_h : g_inp;
    const float* W  = (w_id==0) ? Wext : (w_id==1) ? g_Wcomb : g_Wg;
    const float* Bv = (w_id==0) ? Bext : (w_id==1) ? g_bcomb : g_bg;

    __shared__ unsigned As[2][64][17];
    __shared__ unsigned Ws[2][128][17];
    __shared__ unsigned s_last;

    int tid = threadIdx.x;
    int n0 = blockIdx.x*128;
    int ksplit = gridDim.z;
    int kchunk = K / ksplit;
    int kbeg = blockIdx.z * kchunk, kend = kbeg + kchunk;

    int arow = tid >> 2, acol = (tid & 3) * 4;
    int brow = tid >> 1, bcol = (tid & 1) * 8;
    bool bok = (n0 + brow) < N;
    const float* Ap = A + (size_t)arow*lda + acol;
    const float* Wp = W + (size_t)(n0+brow)*K + bcol;

    int w = tid >> 5, lane = tid & 31, g = lane >> 2, c = lane & 3;
    int wm = (w >> 2) * 32, wn = (w & 3) * 32;

    float acc[2][4][4];
    #pragma unroll
    for (int i=0;i<2;i++)
        #pragma unroll
        for (int j=0;j<4;j++)
            #pragma unroll
            for (int q=0;q<4;q++) acc[i][j][q] = 0.f;

    float4 ra, rb0, rb1;
    ra = *(const float4*)(Ap + kbeg);
    if (bok){ rb0 = *(const float4*)(Wp + kbeg); rb1 = *(const float4*)(Wp + kbeg + 4); }
    else    { rb0 = make_float4(0,0,0,0); rb1 = rb0; }

    for (int k0 = kbeg; k0 < kend; k0 += 16){
        {
            float av[4] = {ra.x, ra.y, ra.z, ra.w};
            #pragma unroll
            for (int j=0;j<4;j++){
                unsigned hi = tf32c(av[j]);
                As[0][arow][acol+j] = hi;
                if (prec) As[1][arow][acol+j] = tf32c(av[j] - __uint_as_float(hi));
            }
            float bv[8] = {rb0.x,rb0.y,rb0.z,rb0.w, rb1.x,rb1.y,rb1.z,rb1.w};
            #pragma unroll
            for (int j=0;j<8;j++){
                unsigned hi = tf32c(bv[j]);
                Ws[0][brow][bcol+j] = hi;
                if (prec) Ws[1][brow][bcol+j] = tf32c(bv[j] - __uint_as_float(hi));
            }
        }
        __syncthreads();
        if (k0 + 16 < kend){
            ra = *(const float4*)(Ap + k0 + 16);
            if (bok){ rb0 = *(const float4*)(Wp + k0 + 16); rb1 = *(const float4*)(Wp + k0 + 20); }
        }
        #pragma unroll
        for (int kq = 0; kq < 2; kq++){
            int k8 = kq*8;
            unsigned ah[2][4], bh[4][2];
            #pragma unroll
            for (int mt=0;mt<2;mt++){
                int rm = wm + mt*16;
                ah[mt][0] = As[0][rm+g  ][k8+c];
                ah[mt][1] = As[0][rm+g+8][k8+c];
                ah[mt][2] = As[0][rm+g  ][k8+c+4];
                ah[mt][3] = As[0][rm+g+8][k8+c+4];
            }
            #pragma unroll
            for (int nt=0;nt<4;nt++){
                int nb = wn + nt*8;
                bh[nt][0] = Ws[0][nb+g][k8+c];
                bh[nt][1] = Ws[0][nb+g][k8+c+4];
            }
            #pragma unroll
            for (int mt=0;mt<2;mt++)
                #pragma unroll
                for (int nt=0;nt<4;nt++)
                    mma8(acc[mt][nt], ah[mt][0],ah[mt][1],ah[mt][2],ah[mt][3], bh[nt][0],bh[nt][1]);
            if (prec){
                unsigned al[2][4], bl[4][2];
                #pragma unroll
                for (int mt=0;mt<2;mt++){
                    int rm = wm + mt*16;
                    al[mt][0] = As[1][rm+g  ][k8+c];
                    al[mt][1] = As[1][rm+g+8][k8+c];
                    al[mt][2] = As[1][rm+g  ][k8+c+4];
                    al[mt][3] = As[1][rm+g+8][k8+c+4];
                }
                #pragma unroll
                for (int nt=0;nt<4;nt++){
                    int nb = wn + nt*8;
                    bl[nt][0] = Ws[1][nb+g][k8+c];
                    bl[nt][1] = Ws[1][nb+g][k8+c+4];
                }
                #pragma unroll
                for (int mt=0;mt<2;mt++)
                    #pragma unroll
                    for (int nt=0;nt<4;nt++){
                        mma8(acc[mt][nt], al[mt][0],al[mt][1],al[mt][2],al[mt][3], bh[nt][0],bh[nt][1]);
                        mma8(acc[mt][nt], ah[mt][0],ah[mt][1],ah[mt][2],ah[mt][3], bl[nt][0],bl[nt][1]);
                    }
            }
        }
        __syncthreads();
    }

    if (ksplit > 1){
        float* pp = &g_part[((size_t)blockIdx.x*8 + blockIdx.z)*8192];
        #pragma unroll
        for (int mt=0;mt<2;mt++)
            #pragma unroll
            for (int nt=0;nt<4;nt++){
                int r1 = wm + mt*16 + g;
                int cc = wn + nt*8 + 2*c;
                pp[r1*128 + cc]     = acc[mt][nt][0];
                pp[r1*128 + cc+1]   = acc[mt][nt][1];
                pp[(r1+8)*128 + cc]   = acc[mt][nt][2];
                pp[(r1+8)*128 + cc+1] = acc[mt][nt][3];
            }
        __threadfence();
        __syncthreads();
        if (tid == 0){
            unsigned v = atomicAdd(&g_cnt[blockIdx.x], 1u);
            s_last = (v == (unsigned)(ksplit-1)) ? 1u : 0u;
        }
        __syncthreads();
        if (!s_last) return;
        __threadfence();
        #pragma unroll
        for (int mt=0;mt<2;mt++)
            #pragma unroll
            for (int nt=0;nt<4;nt++){
                int r1 = wm + mt*16 + g;
                int cc = wn + nt*8 + 2*c;
                float s0=0.f,s1=0.f,s2=0.f,s3=0.f;
                for (int kz = 0; kz < ksplit; kz++){
                    const float* q = &g_part[((size_t)blockIdx.x*8 + kz)*8192];
                    s0 += q[r1*128 + cc];     s1 += q[r1*128 + cc+1];
                    s2 += q[(r1+8)*128 + cc]; s3 += q[(r1+8)*128 + cc+1];
                }
                acc[mt][nt][0]=s0; acc[mt][nt][1]=s1; acc[mt][nt][2]=s2; acc[mt][nt][3]=s3;
            }
        __syncthreads();
        if (tid == 0) g_cnt[blockIdx.x] = 0;
    }

    #pragma unroll
    for (int mt=0;mt<2;mt++)
        #pragma unroll
        for (int nt=0;nt<4;nt++)
            #pragma unroll
            for (int q=0;q<4;q++){
                int r = wm + mt*16 + g + ((q>=2)?8:0);
                int n = n0 + wn + nt*8 + 2*c + (q&1);
                if (n >= N) continue;
                float v = acc[mt][nt][q] + Bv[n];
                if (c_id == 0){
                    g_h[(size_t)r*HH + n] = v;
                } else if (c_id == 1){
                    if (n < EE) g_hwh_h[(size_t)r*EE + n] = __float2half(v);
                    else        g_gate[(size_t)r*EE + (n-EE)] = sigfast(v);
                } else if (c_id == 2){
                    g_gru[(size_t)r*2048 + n] = v;
                } else {
                    if (g_dec[r] >= t)
                        outp[(size_t)r*TCAP*VSZ + (size_t)t*VSZ + n] = v;
                }
            }
}

// ---------------- attention logits: fp16 pipeline, tanh.approx.f16x2 ----------------
__global__ __launch_bounds__(256) void att_kernel(const float* __restrict__ Vw,
                                                  const float* __restrict__ Vb){
    int b = blockIdx.y, p0 = blockIdx.x*4;
    int tid = threadIdx.x;
    const uint4* xbase = (const uint4*)(g_xwx_h + (size_t)(b*PP + p0)*EE);
    uint4 hv = ((const uint4*)(g_hwh_h + (size_t)b*EE))[tid];
    float4 v0 = ((const float4*)Vw)[2*tid];
    float4 v1 = ((const float4*)Vw)[2*tid+1];
    float s[4];
    #pragma unroll
    for (int pp = 0; pp < 4; pp++){
        uint4 xv = xbase[(size_t)pp*(EE/8) + tid];
        unsigned t0 = tanh2(hadd2u(xv.x, hv.x));
        unsigned t1 = tanh2(hadd2u(xv.y, hv.y));
        unsigned t2 = tanh2(hadd2u(xv.z, hv.z));
        unsigned t3 = tanh2(hadd2u(xv.w, hv.w));
        float2 f0 = __half22float2(*(__half2*)&t0);
        float2 f1 = __half22float2(*(__half2*)&t1);
        float2 f2 = __half22float2(*(__half2*)&t2);
        float2 f3 = __half22float2(*(__half2*)&t3);
        float acc = f0.x*v0.x + f0.y*v0.y;
        acc = fmaf(f1.x, v0.z, acc); acc = fmaf(f1.y, v0.w, acc);
        acc = fmaf(f2.x, v1.x, acc); acc = fmaf(f2.y, v1.y, acc);
        acc = fmaf(f3.x, v1.z, acc); acc = fmaf(f3.y, v1.w, acc);
        s[pp] = acc;
    }
    #pragma unroll
    for (int pp = 0; pp < 4; pp++)
        #pragma unroll
        for (int o = 16; o > 0; o >>= 1) s[pp] += __shfl_xor_sync(0xffffffffu, s[pp], o);
    __shared__ float sh[4][8];
    if ((tid & 31) == 0)
        #pragma unroll
        for (int pp = 0; pp < 4; pp++) sh[pp][tid>>5] = s[pp];
    __syncthreads();
    if (tid < 4){
        float tt = 0.f;
        #pragma unroll
        for (int w2 = 0; w2 < 8; w2++) tt += sh[tid][w2];
        g_lam[b*PP + p0 + tid] = tt + Vb[0];
    }
}

// ---------------- fused softmax + z + gate + embed + h-concat ----------------
__global__ __launch_bounds__(256) void zbuild_kernel(const float* __restrict__ feat,
                                                     const int* __restrict__ caps,
                                                     const float* __restrict__ embw,
                                                     float* __restrict__ outp, int t){
    int b = blockIdx.y, tid = threadIdx.x;
    __shared__ float red[256];
    __shared__ float salpha[PP];
    float v = (tid < PP) ? g_lam[b*PP + tid] : -1e30f;
    red[tid] = v; __syncthreads();
    for (int s2 = 128; s2 > 0; s2 >>= 1){ if (tid < s2) red[tid] = fmaxf(red[tid], red[tid+s2]); __syncthreads(); }
    float mx = red[0]; __syncthreads();
    float e = (tid < PP) ? expf(v - mx) : 0.f;
    red[tid] = e; __syncthreads();
    for (int s2 = 128; s2 > 0; s2 >>= 1){ if (tid < s2) red[tid] += red[tid+s2]; __syncthreads(); }
    float inv = 1.f / red[0];
    if (tid < PP) salpha[tid] = e * inv;
    __syncthreads();

    if (blockIdx.x == 0 && tid < PP && g_dec[b] >= t)
        outp[ALPHA_OFF + (size_t)b*TCAP*PP + (size_t)t*PP + tid] = salpha[tid];

    int ecol = blockIdx.x*256 + tid;        // 0..3071
    if (ecol < EE){
        const float* f = feat + (size_t)b*PP*EE + ecol;
        float s = 0.f;
        #pragma unroll 4
        for (int p = 0; p < PP; p++) s = fmaf(salpha[p], f[(size_t)p*EE], s);
        g_inp[(size_t)b*KCAT + ecol] = g_gate[b*EE + ecol] * s;
    } else if (ecol < KIH){
        int tok = caps[b*TCAP + t];
        g_inp[(size_t)b*KCAT + ecol] = embw[(size_t)tok*EMBD + (ecol - EE)];
    } else {
        g_inp[(size_t)b*KCAT + ecol] = g_h[b*HH + (ecol - KIH)];
    }
}

// ---------------- GRU combine + masked h update (precise math) ----------------
__global__ __launch_bounds__(256) void gru_combine(int t){
    int idx = blockIdx.x*256 + threadIdx.x;   // 0..32767
    int b = idx >> 9, j = idx & 511;
    const float* G = g_gru + (size_t)b*2048;
    float r  = sigf(G[j]);
    float z  = sigf(G[512 + j]);
    float n  = tanhf(G[1024 + j] + r * G[1536 + j]);
    float h  = g_h[b*HH + j];
    float hnew = (1.f - z)*n + z*h;
    if (g_dec[b] >= t) g_h[b*HH + j] = hnew;
}

// ---------------- launch ----------------
extern "C" void kernel_launch(void* const* d_in, const int* in_sizes, int n_in,
                              void* d_out, int out_size){
    const float* features = (const float*)d_in[0];
    const int*   captions = (const int*)  d_in[1];
    const int*   lengths  = (const int*)  d_in[2];
    const float* Wx_w  = (const float*)d_in[3];
    const float* Wx_b  = (const float*)d_in[4];
    const float* Wh_w  = (const float*)d_in[5];
    const float* Wh_b  = (const float*)d_in[6];
    const float* V_w   = (const float*)d_in[7];
    const float* V_b   = (const float*)d_in[8];
    const float* ih_w  = (const float*)d_in[9];
    const float* ih_b  = (const float*)d_in[10];
    const float* fb_w  = (const float*)d_in[11];
    const float* fb_b  = (const float*)d_in[12];
    const float* emb_w = (const float*)d_in[13];
    const float* gih_w = (const float*)d_in[14];
    const float* gih_b = (const float*)d_in[15];
    const float* ghh_w = (const float*)d_in[16];
    const float* ghh_b = (const float*)d_in[17];
    const float* fc1_w = (const float*)d_in[18];
    const float* fc1_b = (const float*)d_in[19];
    float* out = (float*)d_out;

    cudaMemsetAsync(d_out, 0, (size_t)out_size * sizeof(float), 0);
    dec_kernel<<<1, 64>>>(lengths, out);
    mean_kernel<<<dim3(EE/256, BB), 256>>>(features);
    build_wcomb<<<(4096*512)/256, 256>>>(Wh_w, Wh_b, fb_w, fb_b);
    build_wg<<<(2048*KCAT)/256, 256>>>(gih_w, gih_b, ghh_w, ghh_b);
    // h0 = fm @ init_h_w^T + b : N=512, K=2048, compensated, split-K 8
    mm_tc<<<dim3(4, 1, 8), 256>>>(0, EE, 0, ih_w, ih_b, 0, HH, EE, 1, out, 0);
    // x_wx: cp.async double-buffered tf32, fp16 output
    xwx_tc<<<dim3(EE/128, BPP/128), 256>>>(features, Wx_w, Wx_b);

    for (int t = 0; t < TMAXX; t++){
        // hwh(fp16) + gate combined: N=4096, K=512, compensated
        mm_tc<<<dim3(32, 1, 4), 256>>>(1, HH, 1, nullptr, nullptr, 1, 4096, HH, 1, out, t);
        att_kernel<<<dim3(PP/4, BB), 256>>>(V_w, V_b);
        zbuild_kernel<<<dim3(KCAT/256, BB), 256>>>(features, captions, emb_w, out, t);
        // combined GRU GEMM: N=2048, K=3072, compensated
        mm_tc<<<dim3(16, 1, 8), 256>>>(2, KCAT, 2, nullptr, nullptr, 2, 2048, KCAT, 1, out, t);
        gru_combine<<<(BB*HH)/256, 256>>>(t);
        // fc1: N=10000, K=512, compensated, masked store to preds
        mm_tc<<<dim3(79, 1, 4), 256>>>(1, HH, 0, fc1_w, fc1_b, 3, VSZ, HH, 1, out, t);
    }
}

// round 5
// speedup vs baseline: 2.6400x; 1.0034x over previous
#include <cuda_runtime.h>
#include <cuda_fp16.h>
#include <math.h>

#define BB    64
#define PP    196
#define EE    2048
#define HH    512
#define EMBD  512
#define VSZ   10000
#define TCAP  50
#define TMAXX 49
#define BPP   (BB*PP)          // 12544
#define KIH   (EE+EMBD)        // 2560
#define KCAT  3072             // EE+EMBD+HH

#define PRED_SZ   ((size_t)BB*TCAP*VSZ)
#define ALPHA_OFF PRED_SZ
#define ALPHA_SZ  ((size_t)BB*TCAP*PP)
#define DEC_OFF   (ALPHA_OFF + ALPHA_SZ)

// ---------------- scratch ----------------
__device__ __half g_xwx_h[(size_t)BPP*EE];      // fp16 attention projections (51MB)
__device__ __half g_hwh_h[BB*EE];
__device__ float g_fm  [BB*EE];
__device__ float g_h   [BB*HH];
__device__ float g_gate[BB*EE];
__device__ float g_lam [BB*PP];
__device__ float g_inp [BB*KCAT];
__device__ float g_gru [BB*2048];
__device__ int   g_dec [BB];
__device__ float g_part[(size_t)79*8*64*128];   // split-K partials
__device__ unsigned int g_cnt[80];              // zero-init; finisher resets
__device__ float g_Wcomb[4096*512];             // [Wh_w ; f_beta_w]
__device__ float g_bcomb[4096];
__device__ float g_Wg[(size_t)2048*KCAT];       // combined GRU weight
__device__ float g_bg[2048];

// ---------------- helpers ----------------
__device__ __forceinline__ unsigned tf32c(float x){
    unsigned r; asm("cvt.rna.tf32.f32 %0, %1;" : "=r"(r) : "f"(x)); return r;
}
__device__ __forceinline__ void mma8(float* c, unsigned a0,unsigned a1,unsigned a2,unsigned a3,
                                     unsigned b0,unsigned b1){
    asm volatile("mma.sync.aligned.m16n8k8.row.col.f32.tf32.tf32.f32 "
        "{%0,%1,%2,%3}, {%4,%5,%6,%7}, {%8,%9}, {%0,%1,%2,%3};"
        : "+f"(c[0]),"+f"(c[1]),"+f"(c[2]),"+f"(c[3])
        : "r"(a0),"r"(a1),"r"(a2),"r"(a3),"r"(b0),"r"(b1));
}
__device__ __forceinline__ unsigned hadd2u(unsigned a, unsigned b){
    unsigned r; asm("add.f16x2 %0,%1,%2;" : "=r"(r) : "r"(a), "r"(b)); return r;
}
__device__ __forceinline__ unsigned tanh2(unsigned x){
    unsigned r; asm("tanh.approx.f16x2 %0,%1;" : "=r"(r) : "r"(x)); return r;
}
__device__ __forceinline__ void cpa16(void* smem, const void* g){
    unsigned sa = (unsigned)__cvta_generic_to_shared(smem);
    asm volatile("cp.async.cg.shared.global [%0], [%1], 16;" :: "r"(sa), "l"(g));
}
__device__ __forceinline__ void cpcommit(){ asm volatile("cp.async.commit_group;"); }
__device__ __forceinline__ void cpwait1(){ asm volatile("cp.async.wait_group 1;"); }
__device__ __forceinline__ float sigf(float x){ return 1.f/(1.f+expf(-x)); }
__device__ __forceinline__ float sigfast(float x){ return 1.f/(1.f+__expf(-x)); }

// ---------------- tiny kernels ----------------
__global__ void dec_kernel(const int* __restrict__ lengths, float* __restrict__ outp){
    int b = threadIdx.x;
    if (b < BB){ int d = lengths[b]-1; g_dec[b] = d; outp[DEC_OFF+b] = (float)d; }
}

__global__ __launch_bounds__(256) void mean_kernel(const float* __restrict__ feat){
    int b = blockIdx.y;
    int e = blockIdx.x*256 + threadIdx.x;
    const float* f = feat + (size_t)b*PP*EE + e;
    float s = 0.f;
    #pragma unroll 4
    for (int p = 0; p < PP; p++) s += f[(size_t)p*EE];
    g_fm[b*EE+e] = s * (1.f/(float)PP);
}

__global__ __launch_bounds__(256) void build_wcomb(const float* __restrict__ Whw, const float* __restrict__ Whb,
                                                   const float* __restrict__ fbw, const float* __restrict__ fbb){
    int idx = blockIdx.x*256 + threadIdx.x;      // 4096*512
    int n = idx >> 9, k = idx & 511;
    g_Wcomb[idx] = (n < EE) ? Whw[n*HH+k] : fbw[(n-EE)*HH+k];
    if (k == 0) g_bcomb[n] = (n < EE) ? Whb[n] : fbb[n-EE];
}

// combined GRU weight (2048 x 3072)
__global__ __launch_bounds__(256) void build_wg(const float* __restrict__ gihw, const float* __restrict__ gihb,
                                                const float* __restrict__ ghhw, const float* __restrict__ ghhb){
    size_t idx = (size_t)blockIdx.x*256 + threadIdx.x;    // 2048*3072
    int n = (int)(idx / KCAT), k = (int)(idx % KCAT);
    float v;
    if (n < 1024)       v = (k < KIH) ? gihw[(size_t)n*KIH+k] : ghhw[(size_t)n*HH + (k-KIH)];
    else if (n < 1536)  v = (k < KIH) ? gihw[(size_t)n*KIH+k] : 0.f;
    else                v = (k < KIH) ? 0.f : ghhw[(size_t)(n-512)*HH + (k-KIH)];
    g_Wg[idx] = v;
    if (k == 0){
        if (n < 1024)      g_bg[n] = gihb[n] + ghhb[n];
        else if (n < 1536) g_bg[n] = gihb[n];
        else               g_bg[n] = ghhb[n-512];
    }
}

// ---------------- big tf32 GEMM with cp.async double buffering ----------------
// xwx = features(12544x2048) @ Wx_w(2048x2048)^T + bias -> fp16 out
// tile 128x128, BK=16, 256 threads, 8 warps as 2(m)x4(n), warp tile 64x32.
#define XS 20
__global__ __launch_bounds__(256) void xwx_tc(const float* __restrict__ A,
                                              const float* __restrict__ W,
                                              const float* __restrict__ bias){
    __shared__ float As[2][128*XS];
    __shared__ float Bs[2][128*XS];
    int tid = threadIdx.x;
    int m0 = blockIdx.y*128, n0 = blockIdx.x*128;

    int rc = tid >> 2, kc = (tid & 3) * 4;     // chunk row / k-offset
    const float* Ap = A + (size_t)(m0+rc)*EE + kc;
    const float* Wp = W + (size_t)(n0+rc)*EE + kc;

    int wq = tid >> 5, lane = tid & 31, g = lane >> 2, ct = lane & 3;
    int wm = (wq >> 2) * 64, wn = (wq & 3) * 32;

    float acc[4][4][4];
    #pragma unroll
    for (int i=0;i<4;i++)
        #pragma unroll
        for (int j=0;j<4;j++)
            #pragma unroll
            for (int q=0;q<4;q++) acc[i][j][q] = 0.f;

    // prologue: stage 0, stage 1
    #pragma unroll
    for (int s = 0; s < 2; s++){
        int k0 = s*16;
        cpa16(&As[s][rc*XS + kc],      Ap + k0);
        cpa16(&As[s][(rc+64)*XS + kc], Ap + (size_t)64*EE + k0);
        cpa16(&Bs[s][rc*XS + kc],      Wp + k0);
        cpa16(&Bs[s][(rc+64)*XS + kc], Wp + (size_t)64*EE + k0);
        cpcommit();
    }

    for (int k0 = 0; k0 < EE; k0 += 16){
        int s = (k0 >> 4) & 1;
        cpwait1();
        __syncthreads();
        const unsigned* Au = (const unsigned*)As[s];
        const unsigned* Bu = (const unsigned*)Bs[s];
        #pragma unroll
        for (int kq = 0; kq < 2; kq++){
            int k8 = kq*8;
            unsigned ah[4][4], bh[4][2];
            #pragma unroll
            for (int mt=0;mt<4;mt++){
                int rm = wm + mt*16;
                ah[mt][0] = Au[(rm+g  )*XS + k8+ct];
                ah[mt][1] = Au[(rm+g+8)*XS + k8+ct];
                ah[mt][2] = Au[(rm+g  )*XS + k8+ct+4];
                ah[mt][3] = Au[(rm+g+8)*XS + k8+ct+4];
            }
            #pragma unroll
            for (int nt=0;nt<4;nt++){
                int nb = wn + nt*8;
                bh[nt][0] = Bu[(nb+g)*XS + k8+ct];
                bh[nt][1] = Bu[(nb+g)*XS + k8+ct+4];
            }
            #pragma unroll
            for (int mt=0;mt<4;mt++)
                #pragma unroll
                for (int nt=0;nt<4;nt++)
                    mma8(acc[mt][nt], ah[mt][0],ah[mt][1],ah[mt][2],ah[mt][3], bh[nt][0],bh[nt][1]);
        }
        __syncthreads();
        if (k0 + 32 < EE){
            int kn = k0 + 32;
            cpa16(&As[s][rc*XS + kc],      Ap + kn);
            cpa16(&As[s][(rc+64)*XS + kc], Ap + (size_t)64*EE + kn);
            cpa16(&Bs[s][rc*XS + kc],      Wp + kn);
            cpa16(&Bs[s][(rc+64)*XS + kc], Wp + (size_t)64*EE + kn);
            cpcommit();
        }
    }

    #pragma unroll
    for (int mt=0;mt<4;mt++){
        #pragma unroll
        for (int nt=0;nt<4;nt++){
            int cn = n0 + wn + nt*8 + 2*ct;
            float b0 = bias[cn], b1 = bias[cn+1];
            size_t r1 = (size_t)(m0 + wm + mt*16 + g);
            __half2 h2a = __floats2half2_rn(acc[mt][nt][0] + b0, acc[mt][nt][1] + b1);
            __half2 h2b = __floats2half2_rn(acc[mt][nt][2] + b0, acc[mt][nt][3] + b1);
            *(__half2*)&g_xwx_h[r1*EE + cn]     = h2a;
            *(__half2*)&g_xwx_h[(r1+8)*EE + cn] = h2b;
        }
    }
}

// ---------------- skinny tensor-core GEMM (M=64), compensated tf32 ----------------
// c_id: 0=g_h 1=hwh(fp16)/gate dual 2=g_gru 3=masked preds
__global__ __launch_bounds__(256) void mm_tc(int a_id, int lda,
                                             int w_id, const float* __restrict__ Wext,
                                             const float* __restrict__ Bext,
                                             int c_id, int N, int K, int prec,
                                             float* __restrict__ outp, int t){
    const float* A  = (a_id==0) ? g_fm : (a_id==1) ? g_h : g_inp;
    const float* W  = (w_id==0) ? Wext : (w_id==1) ? g_Wcomb : g_Wg;
    const float* Bv = (w_id==0) ? Bext : (w_id==1) ? g_bcomb : g_bg;

    __shared__ unsigned As[2][64][17];
    __shared__ unsigned Ws[2][128][17];
    __shared__ unsigned s_last;

    int tid = threadIdx.x;
    int n0 = blockIdx.x*128;
    int ksplit = gridDim.z;
    int kchunk = K / ksplit;
    int kbeg = blockIdx.z * kchunk, kend = kbeg + kchunk;

    int arow = tid >> 2, acol = (tid & 3) * 4;
    int brow = tid >> 1, bcol = (tid & 1) * 8;
    bool bok = (n0 + brow) < N;
    const float* Ap = A + (size_t)arow*lda + acol;
    const float* Wp = W + (size_t)(n0+brow)*K + bcol;

    int w = tid >> 5, lane = tid & 31, g = lane >> 2, c = lane & 3;
    int wm = (w >> 2) * 32, wn = (w & 3) * 32;

    float acc[2][4][4];
    #pragma unroll
    for (int i=0;i<2;i++)
        #pragma unroll
        for (int j=0;j<4;j++)
            #pragma unroll
            for (int q=0;q<4;q++) acc[i][j][q] = 0.f;

    float4 ra, rb0, rb1;
    ra = *(const float4*)(Ap + kbeg);
    if (bok){ rb0 = *(const float4*)(Wp + kbeg); rb1 = *(const float4*)(Wp + kbeg + 4); }
    else    { rb0 = make_float4(0,0,0,0); rb1 = rb0; }

    for (int k0 = kbeg; k0 < kend; k0 += 16){
        {
            float av[4] = {ra.x, ra.y, ra.z, ra.w};
            #pragma unroll
            for (int j=0;j<4;j++){
                unsigned hi = tf32c(av[j]);
                As[0][arow][acol+j] = hi;
                if (prec) As[1][arow][acol+j] = tf32c(av[j] - __uint_as_float(hi));
            }
            float bv[8] = {rb0.x,rb0.y,rb0.z,rb0.w, rb1.x,rb1.y,rb1.z,rb1.w};
            #pragma unroll
            for (int j=0;j<8;j++){
                unsigned hi = tf32c(bv[j]);
                Ws[0][brow][bcol+j] = hi;
                if (prec) Ws[1][brow][bcol+j] = tf32c(bv[j] - __uint_as_float(hi));
            }
        }
        __syncthreads();
        if (k0 + 16 < kend){
            ra = *(const float4*)(Ap + k0 + 16);
            if (bok){ rb0 = *(const float4*)(Wp + k0 + 16); rb1 = *(const float4*)(Wp + k0 + 20); }
        }
        #pragma unroll
        for (int kq = 0; kq < 2; kq++){
            int k8 = kq*8;
            unsigned ah[2][4], bh[4][2];
            #pragma unroll
            for (int mt=0;mt<2;mt++){
                int rm = wm + mt*16;
                ah[mt][0] = As[0][rm+g  ][k8+c];
                ah[mt][1] = As[0][rm+g+8][k8+c];
                ah[mt][2] = As[0][rm+g  ][k8+c+4];
                ah[mt][3] = As[0][rm+g+8][k8+c+4];
            }
            #pragma unroll
            for (int nt=0;nt<4;nt++){
                int nb = wn + nt*8;
                bh[nt][0] = Ws[0][nb+g][k8+c];
                bh[nt][1] = Ws[0][nb+g][k8+c+4];
            }
            #pragma unroll
            for (int mt=0;mt<2;mt++)
                #pragma unroll
                for (int nt=0;nt<4;nt++)
                    mma8(acc[mt][nt], ah[mt][0],ah[mt][1],ah[mt][2],ah[mt][3], bh[nt][0],bh[nt][1]);
            if (prec){
                unsigned al[2][4], bl[4][2];
                #pragma unroll
                for (int mt=0;mt<2;mt++){
                    int rm = wm + mt*16;
                    al[mt][0] = As[1][rm+g  ][k8+c];
                    al[mt][1] = As[1][rm+g+8][k8+c];
                    al[mt][2] = As[1][rm+g  ][k8+c+4];
                    al[mt][3] = As[1][rm+g+8][k8+c+4];
                }
                #pragma unroll
                for (int nt=0;nt<4;nt++){
                    int nb = wn + nt*8;
                    bl[nt][0] = Ws[1][nb+g][k8+c];
                    bl[nt][1] = Ws[1][nb+g][k8+c+4];
                }
                #pragma unroll
                for (int mt=0;mt<2;mt++)
                    #pragma unroll
                    for (int nt=0;nt<4;nt++){
                        mma8(acc[mt][nt], al[mt][0],al[mt][1],al[mt][2],al[mt][3], bh[nt][0],bh[nt][1]);
                        mma8(acc[mt][nt], ah[mt][0],ah[mt][1],ah[mt][2],ah[mt][3], bl[nt][0],bl[nt][1]);
                    }
            }
        }
        __syncthreads();
    }

    if (ksplit > 1){
        float* pp = &g_part[((size_t)blockIdx.x*8 + blockIdx.z)*8192];
        #pragma unroll
        for (int mt=0;mt<2;mt++)
            #pragma unroll
            for (int nt=0;nt<4;nt++){
                int r1 = wm + mt*16 + g;
                int cc = wn + nt*8 + 2*c;
                pp[r1*128 + cc]     = acc[mt][nt][0];
                pp[r1*128 + cc+1]   = acc[mt][nt][1];
                pp[(r1+8)*128 + cc]   = acc[mt][nt][2];
                pp[(r1+8)*128 + cc+1] = acc[mt][nt][3];
            }
        __threadfence();
        __syncthreads();
        if (tid == 0){
            unsigned v = atomicAdd(&g_cnt[blockIdx.x], 1u);
            s_last = (v == (unsigned)(ksplit-1)) ? 1u : 0u;
        }
        __syncthreads();
        if (!s_last) return;
        __threadfence();
        #pragma unroll
        for (int mt=0;mt<2;mt++)
            #pragma unroll
            for (int nt=0;nt<4;nt++){
                int r1 = wm + mt*16 + g;
                int cc = wn + nt*8 + 2*c;
                float s0=0.f,s1=0.f,s2=0.f,s3=0.f;
                for (int kz = 0; kz < ksplit; kz++){
                    const float* q = &g_part[((size_t)blockIdx.x*8 + kz)*8192];
                    s0 += q[r1*128 + cc];     s1 += q[r1*128 + cc+1];
                    s2 += q[(r1+8)*128 + cc]; s3 += q[(r1+8)*128 + cc+1];
                }
                acc[mt][nt][0]=s0; acc[mt][nt][1]=s1; acc[mt][nt][2]=s2; acc[mt][nt][3]=s3;
            }
        __syncthreads();
        if (tid == 0) g_cnt[blockIdx.x] = 0;
    }

    #pragma unroll
    for (int mt=0;mt<2;mt++)
        #pragma unroll
        for (int nt=0;nt<4;nt++)
            #pragma unroll
            for (int q=0;q<4;q++){
                int r = wm + mt*16 + g + ((q>=2)?8:0);
                int n = n0 + wn + nt*8 + 2*c + (q&1);
                if (n >= N) continue;
                float v = acc[mt][nt][q] + Bv[n];
                if (c_id == 0){
                    g_h[(size_t)r*HH + n] = v;
                } else if (c_id == 1){
                    if (n < EE) g_hwh_h[(size_t)r*EE + n] = __float2half(v);
                    else        g_gate[(size_t)r*EE + (n-EE)] = sigfast(v);
                } else if (c_id == 2){
                    g_gru[(size_t)r*2048 + n] = v;
                } else {
                    if (g_dec[r] >= t)
                        outp[(size_t)r*TCAP*VSZ + (size_t)t*VSZ + n] = v;
                }
            }
}

// ---------------- attention logits: fp16 pipeline, tanh.approx.f16x2 ----------------
__global__ __launch_bounds__(256) void att_kernel(const float* __restrict__ Vw,
                                                  const float* __restrict__ Vb){
    int b = blockIdx.y, p0 = blockIdx.x*4;
    int tid = threadIdx.x;
    const uint4* xbase = (const uint4*)(g_xwx_h + (size_t)(b*PP + p0)*EE);
    uint4 hv = ((const uint4*)(g_hwh_h + (size_t)b*EE))[tid];
    float4 v0 = ((const float4*)Vw)[2*tid];
    float4 v1 = ((const float4*)Vw)[2*tid+1];
    float s[4];
    #pragma unroll
    for (int pp = 0; pp < 4; pp++){
        uint4 xv = xbase[(size_t)pp*(EE/8) + tid];
        unsigned t0 = tanh2(hadd2u(xv.x, hv.x));
        unsigned t1 = tanh2(hadd2u(xv.y, hv.y));
        unsigned t2 = tanh2(hadd2u(xv.z, hv.z));
        unsigned t3 = tanh2(hadd2u(xv.w, hv.w));
        float2 f0 = __half22float2(*(__half2*)&t0);
        float2 f1 = __half22float2(*(__half2*)&t1);
        float2 f2 = __half22float2(*(__half2*)&t2);
        float2 f3 = __half22float2(*(__half2*)&t3);
        float acc = f0.x*v0.x + f0.y*v0.y;
        acc = fmaf(f1.x, v0.z, acc); acc = fmaf(f1.y, v0.w, acc);
        acc = fmaf(f2.x, v1.x, acc); acc = fmaf(f2.y, v1.y, acc);
        acc = fmaf(f3.x, v1.z, acc); acc = fmaf(f3.y, v1.w, acc);
        s[pp] = acc;
    }
    #pragma unroll
    for (int pp = 0; pp < 4; pp++)
        #pragma unroll
        for (int o = 16; o > 0; o >>= 1) s[pp] += __shfl_xor_sync(0xffffffffu, s[pp], o);
    __shared__ float sh[4][8];
    if ((tid & 31) == 0)
        #pragma unroll
        for (int pp = 0; pp < 4; pp++) sh[pp][tid>>5] = s[pp];
    __syncthreads();
    if (tid < 4){
        float tt = 0.f;
        #pragma unroll
        for (int w2 = 0; w2 < 8; w2++) tt += sh[tid][w2];
        g_lam[b*PP + p0 + tid] = tt + Vb[0];
    }
}

// ---------------- fused softmax + z + gate + embed + h-concat ----------------
__global__ __launch_bounds__(256) void zbuild_kernel(const float* __restrict__ feat,
                                                     const int* __restrict__ caps,
                                                     const float* __restrict__ embw,
                                                     float* __restrict__ outp, int t){
    int b = blockIdx.y, tid = threadIdx.x;
    __shared__ float red[256];
    __shared__ float salpha[PP];
    float v = (tid < PP) ? g_lam[b*PP + tid] : -1e30f;
    red[tid] = v; __syncthreads();
    for (int s2 = 128; s2 > 0; s2 >>= 1){ if (tid < s2) red[tid] = fmaxf(red[tid], red[tid+s2]); __syncthreads(); }
    float mx = red[0]; __syncthreads();
    float e = (tid < PP) ? expf(v - mx) : 0.f;
    red[tid] = e; __syncthreads();
    for (int s2 = 128; s2 > 0; s2 >>= 1){ if (tid < s2) red[tid] += red[tid+s2]; __syncthreads(); }
    float inv = 1.f / red[0];
    if (tid < PP) salpha[tid] = e * inv;
    __syncthreads();

    if (blockIdx.x == 0 && tid < PP && g_dec[b] >= t)
        outp[ALPHA_OFF + (size_t)b*TCAP*PP + (size_t)t*PP + tid] = salpha[tid];

    int ecol = blockIdx.x*256 + tid;        // 0..3071
    if (ecol < EE){
        const float* f = feat + (size_t)b*PP*EE + ecol;
        float s = 0.f;
        #pragma unroll 4
        for (int p = 0; p < PP; p++) s = fmaf(salpha[p], f[(size_t)p*EE], s);
        g_inp[(size_t)b*KCAT + ecol] = g_gate[b*EE + ecol] * s;
    } else if (ecol < KIH){
        int tok = caps[b*TCAP + t];
        g_inp[(size_t)b*KCAT + ecol] = embw[(size_t)tok*EMBD + (ecol - EE)];
    } else {
        g_inp[(size_t)b*KCAT + ecol] = g_h[b*HH + (ecol - KIH)];
    }
}

// ---------------- GRU combine + masked h update (precise math) ----------------
__global__ __launch_bounds__(256) void gru_combine(int t){
    int idx = blockIdx.x*256 + threadIdx.x;   // 0..32767
    int b = idx >> 9, j = idx & 511;
    const float* G = g_gru + (size_t)b*2048;
    float r  = sigf(G[j]);
    float z  = sigf(G[512 + j]);
    float n  = tanhf(G[1024 + j] + r * G[1536 + j]);
    float h  = g_h[b*HH + j];
    float hnew = (1.f - z)*n + z*h;
    if (g_dec[b] >= t) g_h[b*HH + j] = hnew;
}

// ---------------- launch ----------------
extern "C" void kernel_launch(void* const* d_in, const int* in_sizes, int n_in,
                              void* d_out, int out_size){
    const float* features = (const float*)d_in[0];
    const int*   captions = (const int*)  d_in[1];
    const int*   lengths  = (const int*)  d_in[2];
    const float* Wx_w  = (const float*)d_in[3];
    const float* Wx_b  = (const float*)d_in[4];
    const float* Wh_w  = (const float*)d_in[5];
    const float* Wh_b  = (const float*)d_in[6];
    const float* V_w   = (const float*)d_in[7];
    const float* V_b   = (const float*)d_in[8];
    const float* ih_w  = (const float*)d_in[9];
    const float* ih_b  = (const float*)d_in[10];
    const float* fb_w  = (const float*)d_in[11];
    const float* fb_b  = (const float*)d_in[12];
    const float* emb_w = (const float*)d_in[13];
    const float* gih_w = (const float*)d_in[14];
    const float* gih_b = (const float*)d_in[15];
    const float* ghh_w = (const float*)d_in[16];
    const float* ghh_b = (const float*)d_in[17];
    const float* fc1_w = (const float*)d_in[18];
    const float* fc1_b = (const float*)d_in[19];
    float* out = (float*)d_out;

    cudaMemsetAsync(d_out, 0, (size_t)out_size * sizeof(float), 0);
    dec_kernel<<<1, 64>>>(lengths, out);
    mean_kernel<<<dim3(EE/256, BB), 256>>>(features);
    build_wcomb<<<(4096*512)/256, 256>>>(Wh_w, Wh_b, fb_w, fb_b);
    build_wg<<<(2048*KCAT)/256, 256>>>(gih_w, gih_b, ghh_w, ghh_b);
    // h0 = fm @ init_h_w^T + b : N=512, K=2048, compensated, split-K 8
    mm_tc<<<dim3(4, 1, 8), 256>>>(0, EE, 0, ih_w, ih_b, 0, HH, EE, 1, out, 0);
    // x_wx: cp.async double-buffered tf32, fp16 output
    xwx_tc<<<dim3(EE/128, BPP/128), 256>>>(features, Wx_w, Wx_b);

    for (int t = 0; t < TMAXX; t++){
        // hwh(fp16) + gate combined: N=4096, K=512, compensated
        mm_tc<<<dim3(32, 1, 4), 256>>>(1, HH, 1, nullptr, nullptr, 1, 4096, HH, 1, out, t);
        att_kernel<<<dim3(PP/4, BB), 256>>>(V_w, V_b);
        zbuild_kernel<<<dim3(KCAT/256, BB), 256>>>(features, captions, emb_w, out, t);
        // combined GRU GEMM: N=2048, K=3072, compensated
        mm_tc<<<dim3(16, 1, 8), 256>>>(2, KCAT, 2, nullptr, nullptr, 2, 2048, KCAT, 1, out, t);
        gru_combine<<<(BB*HH)/256, 256>>>(t);
        // fc1: N=10000, K=512, compensated, masked store to preds
        mm_tc<<<dim3(79, 1, 4), 256>>>(1, HH, 0, fc1_w, fc1_b, 3, VSZ, HH, 1, out, t);
    }
}

// round 6
// speedup vs baseline: 3.0062x; 1.1387x over previous
#include <cuda_runtime.h>
#include <cuda_fp16.h>
#include <math.h>

#define BB    64
#define PP    196
#define EE    2048
#define HH    512
#define EMBD  512
#define VSZ   10000
#define TCAP  50
#define TMAXX 49
#define BPP   (BB*PP)
#define KIH   (EE+EMBD)       // 2560
#define KCAT  3072            // EE+EMBD+HH

#define PRED_SZ   ((size_t)BB*TCAP*VSZ)
#define ALPHA_OFF PRED_SZ
#define ALPHA_SZ  ((size_t)BB*TCAP*PP)
#define DEC_OFF   (ALPHA_OFF + ALPHA_SZ)

// ---------------- scratch ----------------
__device__ __half g_xwx_h[(size_t)BPP*EE];     // fp16 attention projections
__device__ __half g_feat_h[(size_t)BPP*EE];    // fp16 features copy
__device__ __half g_hwh_h[BB*EE];
__device__ float g_fm  [BB*EE];
__device__ float g_h   [BB*HH];
__device__ float g_gate[BB*EE];
__device__ float g_lam [BB*PP];
__device__ float g_inp [BB*KCAT];
__device__ int   g_dec [BB];
__device__ float g_part[(size_t)111*8*8192];
__device__ unsigned g_cnt[128];                // zero-init; finisher resets
__device__ float g_Wcomb[4096*512];            // [Wh_w ; f_beta_w]
__device__ float g_bcomb[4096];
__device__ float g_Wg[(size_t)2048*KCAT];      // gate-interleaved GRU weight
__device__ float g_bg[2048];

// ---------------- helpers ----------------
__device__ __forceinline__ unsigned tf32c(float x){
    unsigned r; asm("cvt.rna.tf32.f32 %0, %1;" : "=r"(r) : "f"(x)); return r;
}
__device__ __forceinline__ void mma8(float* c, unsigned a0,unsigned a1,unsigned a2,unsigned a3,
                                     unsigned b0,unsigned b1){
    asm volatile("mma.sync.aligned.m16n8k8.row.col.f32.tf32.tf32.f32 "
        "{%0,%1,%2,%3}, {%4,%5,%6,%7}, {%8,%9}, {%0,%1,%2,%3};"
        : "+f"(c[0]),"+f"(c[1]),"+f"(c[2]),"+f"(c[3])
        : "r"(a0),"r"(a1),"r"(a2),"r"(a3),"r"(b0),"r"(b1));
}
__device__ __forceinline__ unsigned hadd2u(unsigned a, unsigned b){
    unsigned r; asm("add.f16x2 %0,%1,%2;" : "=r"(r) : "r"(a), "r"(b)); return r;
}
__device__ __forceinline__ unsigned tanh2(unsigned x){
    unsigned r; asm("tanh.approx.f16x2 %0,%1;" : "=r"(r) : "r"(x)); return r;
}
__device__ __forceinline__ void cpa16(void* smem, const void* g){
    unsigned sa = (unsigned)__cvta_generic_to_shared(smem);
    asm volatile("cp.async.cg.shared.global [%0], [%1], 16;" :: "r"(sa), "l"(g));
}
__device__ __forceinline__ void cpcommit(){ asm volatile("cp.async.commit_group;"); }
__device__ __forceinline__ void cpwait1(){ asm volatile("cp.async.wait_group 1;"); }
__device__ __forceinline__ float sigf(float x){ return 1.f/(1.f+expf(-x)); }
__device__ __forceinline__ float sigfast(float x){ return 1.f/(1.f+__expf(-x)); }

// ---------------- preamble ----------------
__global__ void dec_kernel(const int* __restrict__ lengths, float* __restrict__ outp){
    int b = threadIdx.x;
    if (b < BB){ int d = lengths[b]-1; g_dec[b] = d; outp[DEC_OFF+b] = (float)d; }
}

__global__ __launch_bounds__(256) void mean_kernel(const float* __restrict__ feat){
    int b = blockIdx.y;
    int e = blockIdx.x*256 + threadIdx.x;
    const float* f = feat + (size_t)b*PP*EE + e;
    float s = 0.f;
    #pragma unroll 4
    for (int p = 0; p < PP; p++) s += f[(size_t)p*EE];
    g_fm[b*EE+e] = s * (1.f/(float)PP);
}

__global__ __launch_bounds__(256) void feat2h(const float* __restrict__ f){
    size_t i = (size_t)blockIdx.x*256 + threadIdx.x;   // over BPP*EE/2 half2
    float2 v = ((const float2*)f)[i];
    ((__half2*)g_feat_h)[i] = __floats2half2_rn(v.x, v.y);
}

__global__ __launch_bounds__(256) void build_wcomb(const float* __restrict__ Whw, const float* __restrict__ Whb,
                                                   const float* __restrict__ fbw, const float* __restrict__ fbb){
    int idx = blockIdx.x*256 + threadIdx.x;      // 4096*512
    int n = idx >> 9, k = idx & 511;
    g_Wcomb[idx] = (n < EE) ? Whw[n*HH+k] : fbw[(n-EE)*HH+k];
    if (k == 0) g_bcomb[n] = (n < EE) ? Whb[n] : fbb[n-EE];
}

// gate-interleaved GRU weight: new row m = j*4+q, q in {r,z,n,hn}
__global__ __launch_bounds__(256) void build_wg(const float* __restrict__ gihw, const float* __restrict__ gihb,
                                                const float* __restrict__ ghhw, const float* __restrict__ ghhb){
    size_t idx = (size_t)blockIdx.x*256 + threadIdx.x;    // 2048*3072
    int m = (int)(idx / KCAT), k = (int)(idx % KCAT);
    int j = m >> 2, q = m & 3;
    int n = q*512 + j;         // old row in [0,2048)
    float v;
    if (n < 1024)       v = (k < KIH) ? gihw[(size_t)n*KIH+k] : ghhw[(size_t)n*HH + (k-KIH)];
    else if (n < 1536)  v = (k < KIH) ? gihw[(size_t)n*KIH+k] : 0.f;
    else                v = (k < KIH) ? 0.f : ghhw[(size_t)(n-512)*HH + (k-KIH)];
    g_Wg[idx] = v;
    if (k == 0){
        float bb;
        if (n < 1024)      bb = gihb[n] + ghhb[n];
        else if (n < 1536) bb = gihb[n];
        else               bb = ghhb[n-512];
        g_bg[m] = bb;
    }
}

// h0: precise fp32 dot, one warp per output
__global__ __launch_bounds__(256) void h0_kernel(const float* __restrict__ W,
                                                 const float* __restrict__ bv){
    int gw = blockIdx.x*8 + (threadIdx.x >> 5);
    int lane = threadIdx.x & 31;
    int b = gw >> 9, n = gw & 511;
    const float* a = g_fm + (size_t)b*EE;
    const float* w = W + (size_t)n*EE;
    float s = 0.f;
    #pragma unroll 4
    for (int k = lane; k < EE; k += 32) s = fmaf(a[k], w[k], s);
    #pragma unroll
    for (int o = 16; o > 0; o >>= 1) s += __shfl_xor_sync(0xffffffffu, s, o);
    if (lane == 0) g_h[b*HH + n] = s + bv[n];
}

// ---------------- xwx: tf32 cp.async double-buffered GEMM -> fp16 ----------------
#define XS 20
__global__ __launch_bounds__(256) void xwx_tc(const float* __restrict__ A,
                                              const float* __restrict__ W,
                                              const float* __restrict__ bias){
    __shared__ float As[2][128*XS];
    __shared__ float Bs[2][128*XS];
    int tid = threadIdx.x;
    int m0 = blockIdx.y*128, n0 = blockIdx.x*128;
    int rc = tid >> 2, kc = (tid & 3) * 4;
    const float* Ap = A + (size_t)(m0+rc)*EE + kc;
    const float* Wp = W + (size_t)(n0+rc)*EE + kc;
    int wq = tid >> 5, lane = tid & 31, g = lane >> 2, ct = lane & 3;
    int wm = (wq >> 2) * 64, wn = (wq & 3) * 32;
    float acc[4][4][4];
    #pragma unroll
    for (int i=0;i<4;i++)
        #pragma unroll
        for (int j=0;j<4;j++)
            #pragma unroll
            for (int q=0;q<4;q++) acc[i][j][q] = 0.f;
    #pragma unroll
    for (int s = 0; s < 2; s++){
        int k0 = s*16;
        cpa16(&As[s][rc*XS + kc],      Ap + k0);
        cpa16(&As[s][(rc+64)*XS + kc], Ap + (size_t)64*EE + k0);
        cpa16(&Bs[s][rc*XS + kc],      Wp + k0);
        cpa16(&Bs[s][(rc+64)*XS + kc], Wp + (size_t)64*EE + k0);
        cpcommit();
    }
    for (int k0 = 0; k0 < EE; k0 += 16){
        int s = (k0 >> 4) & 1;
        cpwait1();
        __syncthreads();
        const unsigned* Au = (const unsigned*)As[s];
        const unsigned* Bu = (const unsigned*)Bs[s];
        #pragma unroll
        for (int kq = 0; kq < 2; kq++){
            int k8 = kq*8;
            unsigned ah[4][4], bh[4][2];
            #pragma unroll
            for (int mt=0;mt<4;mt++){
                int rm = wm + mt*16;
                ah[mt][0] = Au[(rm+g  )*XS + k8+ct];
                ah[mt][1] = Au[(rm+g+8)*XS + k8+ct];
                ah[mt][2] = Au[(rm+g  )*XS + k8+ct+4];
                ah[mt][3] = Au[(rm+g+8)*XS + k8+ct+4];
            }
            #pragma unroll
            for (int nt=0;nt<4;nt++){
                int nb = wn + nt*8;
                bh[nt][0] = Bu[(nb+g)*XS + k8+ct];
                bh[nt][1] = Bu[(nb+g)*XS + k8+ct+4];
            }
            #pragma unroll
            for (int mt=0;mt<4;mt++)
                #pragma unroll
                for (int nt=0;nt<4;nt++)
                    mma8(acc[mt][nt], ah[mt][0],ah[mt][1],ah[mt][2],ah[mt][3], bh[nt][0],bh[nt][1]);
        }
        __syncthreads();
        if (k0 + 32 < EE){
            int kn = k0 + 32;
            cpa16(&As[s][rc*XS + kc],      Ap + kn);
            cpa16(&As[s][(rc+64)*XS + kc], Ap + (size_t)64*EE + kn);
            cpa16(&Bs[s][rc*XS + kc],      Wp + kn);
            cpa16(&Bs[s][(rc+64)*XS + kc], Wp + (size_t)64*EE + kn);
            cpcommit();
        }
    }
    #pragma unroll
    for (int mt=0;mt<4;mt++)
        #pragma unroll
        for (int nt=0;nt<4;nt++){
            int cn = n0 + wn + nt*8 + 2*ct;
            float b0 = bias[cn], b1 = bias[cn+1];
            size_t r1 = (size_t)(m0 + wm + mt*16 + g);
            *(__half2*)&g_xwx_h[r1*EE + cn]     = __floats2half2_rn(acc[mt][nt][0]+b0, acc[mt][nt][1]+b1);
            *(__half2*)&g_xwx_h[(r1+8)*EE + cn] = __floats2half2_rn(acc[mt][nt][2]+b0, acc[mt][nt][3]+b1);
        }
}

// ---------------- shared 64x128 compensated-tf32 tile body ----------------
__device__ __forceinline__ void mm_body(const float* __restrict__ A, int lda,
                                        const float* __restrict__ W0, int wrows, int K,
                                        int kbeg, int kend,
                                        unsigned (*As)[64][17], unsigned (*Ws)[128][17],
                                        float acc[2][4][4]){
    int tid = threadIdx.x;
    int arow = tid >> 2, acol = (tid & 3) * 4;
    int brow = tid >> 1, bcol = (tid & 1) * 8;
    bool bok = brow < wrows;
    const float* Ap = A + (size_t)arow*lda + acol;
    const float* Wp = W0 + (size_t)brow*K + bcol;
    int w = tid >> 5, lane = tid & 31, g = lane >> 2, c = lane & 3;
    int wm = (w >> 2) * 32, wn = (w & 3) * 32;
    float4 ra = *(const float4*)(Ap + kbeg);
    float4 rb0 = make_float4(0,0,0,0), rb1 = rb0;
    if (bok){ rb0 = *(const float4*)(Wp + kbeg); rb1 = *(const float4*)(Wp + kbeg + 4); }
    for (int k0 = kbeg; k0 < kend; k0 += 16){
        float av[4] = {ra.x,ra.y,ra.z,ra.w};
        #pragma unroll
        for (int j=0;j<4;j++){
            unsigned hi = tf32c(av[j]);
            As[0][arow][acol+j] = hi;
            As[1][arow][acol+j] = tf32c(av[j] - __uint_as_float(hi));
        }
        float bvv[8] = {rb0.x,rb0.y,rb0.z,rb0.w, rb1.x,rb1.y,rb1.z,rb1.w};
        #pragma unroll
        for (int j=0;j<8;j++){
            unsigned hi = tf32c(bvv[j]);
            Ws[0][brow][bcol+j] = hi;
            Ws[1][brow][bcol+j] = tf32c(bvv[j] - __uint_as_float(hi));
        }
        __syncthreads();
        if (k0 + 16 < kend){
            ra = *(const float4*)(Ap + k0 + 16);
            if (bok){ rb0 = *(const float4*)(Wp + k0 + 16); rb1 = *(const float4*)(Wp + k0 + 20); }
        }
        #pragma unroll
        for (int kq = 0; kq < 2; kq++){
            int k8 = kq*8;
            unsigned ah[2][4], al[2][4], bh[4][2], bl[4][2];
            #pragma unroll
            for (int mt=0;mt<2;mt++){
                int rm = wm + mt*16;
                ah[mt][0]=(*As)[0][0]; // placeholder avoided
                ah[mt][0]=As[0][rm+g][k8+c];   ah[mt][1]=As[0][rm+g+8][k8+c];
                ah[mt][2]=As[0][rm+g][k8+c+4]; ah[mt][3]=As[0][rm+g+8][k8+c+4];
                al[mt][0]=As[1][rm+g][k8+c];   al[mt][1]=As[1][rm+g+8][k8+c];
                al[mt][2]=As[1][rm+g][k8+c+4]; al[mt][3]=As[1][rm+g+8][k8+c+4];
            }
            #pragma unroll
            for (int nt=0;nt<4;nt++){
                int nb = wn + nt*8;
                bh[nt][0]=Ws[0][nb+g][k8+c]; bh[nt][1]=Ws[0][nb+g][k8+c+4];
                bl[nt][0]=Ws[1][nb+g][k8+c]; bl[nt][1]=Ws[1][nb+g][k8+c+4];
            }
            #pragma unroll
            for (int mt=0;mt<2;mt++)
                #pragma unroll
                for (int nt=0;nt<4;nt++){
                    mma8(acc[mt][nt], ah[mt][0],ah[mt][1],ah[mt][2],ah[mt][3], bh[nt][0],bh[nt][1]);
                    mma8(acc[mt][nt], al[mt][0],al[mt][1],al[mt][2],al[mt][3], bh[nt][0],bh[nt][1]);
                    mma8(acc[mt][nt], ah[mt][0],ah[mt][1],ah[mt][2],ah[mt][3], bl[nt][0],bl[nt][1]);
                }
        }
        __syncthreads();
    }
}

// split-K partial store + deterministic finisher reduce. Returns true on finisher.
__device__ bool splitk_reduce(float acc[2][4][4], int slot, int ksplit){
    __shared__ unsigned s_last;
    int tid = threadIdx.x;
    int w = tid >> 5, lane = tid & 31, g = lane >> 2, c = lane & 3;
    int wm = (w >> 2) * 32, wn = (w & 3) * 32;
    float* pp = &g_part[((size_t)slot*8 + blockIdx.z)*8192];
    #pragma unroll
    for (int mt=0;mt<2;mt++)
        #pragma unroll
        for (int nt=0;nt<4;nt++){
            int r1 = wm + mt*16 + g;
            int cc = wn + nt*8 + 2*c;
            pp[r1*128 + cc]       = acc[mt][nt][0];
            pp[r1*128 + cc+1]     = acc[mt][nt][1];
            pp[(r1+8)*128 + cc]   = acc[mt][nt][2];
            pp[(r1+8)*128 + cc+1] = acc[mt][nt][3];
        }
    __threadfence();
    __syncthreads();
    if (tid == 0)
        s_last = (atomicAdd(&g_cnt[slot], 1u) == (unsigned)(ksplit-1)) ? 1u : 0u;
    __syncthreads();
    if (!s_last) return false;
    __threadfence();
    #pragma unroll
    for (int mt=0;mt<2;mt++)
        #pragma unroll
        for (int nt=0;nt<4;nt++){
            int r1 = wm + mt*16 + g;
            int cc = wn + nt*8 + 2*c;
            float s0=0.f,s1=0.f,s2=0.f,s3=0.f;
            for (int kz = 0; kz < ksplit; kz++){
                const float* q = &g_part[((size_t)slot*8 + kz)*8192];
                s0 += q[r1*128 + cc];     s1 += q[r1*128 + cc+1];
                s2 += q[(r1+8)*128 + cc]; s3 += q[(r1+8)*128 + cc+1];
            }
            acc[mt][nt][0]=s0; acc[mt][nt][1]=s1; acc[mt][nt][2]=s2; acc[mt][nt][3]=s3;
        }
    __syncthreads();
    if (tid == 0) g_cnt[slot] = 0;
    return true;
}

// ---------------- wstep: hwh/gate(t) tiles + fc1(t-1) tiles, split-K 2 ----------------
__global__ __launch_bounds__(256) void wstep(const float* __restrict__ fc1w,
                                             const float* __restrict__ fc1b,
                                             float* __restrict__ outp, int t){
    int tile = blockIdx.x;              // 0..110
    bool isC = tile < 32;
    if (isC  && t == TMAXX) return;
    if (!isC && t == 0)     return;
    __shared__ unsigned As[2][64][17];
    __shared__ unsigned Ws[2][128][17];
    int n0 = isC ? tile*128 : (tile-32)*128;
    const float* W = isC ? (g_Wcomb + (size_t)n0*HH) : (fc1w + (size_t)n0*HH);
    int wrows = isC ? 128 : (VSZ - n0 < 128 ? VSZ - n0 : 128);
    float acc[2][4][4];
    #pragma unroll
    for (int i=0;i<2;i++)
        #pragma unroll
        for (int j=0;j<4;j++)
            #pragma unroll
            for (int q=0;q<4;q++) acc[i][j][q]=0.f;
    int kb = blockIdx.z * (HH/2);
    mm_body(g_h, HH, W, wrows, HH, kb, kb + HH/2, As, Ws, acc);
    if (!splitk_reduce(acc, tile, 2)) return;

    int tid = threadIdx.x;
    int w = tid >> 5, lane = tid & 31, g = lane >> 2, c = lane & 3;
    int wm = (w >> 2) * 32, wn = (w & 3) * 32;
    int tt = t - 1;
    #pragma unroll
    for (int mt=0;mt<2;mt++)
        #pragma unroll
        for (int nt=0;nt<4;nt++)
            #pragma unroll
            for (int q=0;q<4;q++){
                int r = wm + mt*16 + g + ((q>=2)?8:0);
                int n = n0 + wn + nt*8 + 2*c + (q&1);
                if (isC){
                    float v = acc[mt][nt][q] + g_bcomb[n];
                    if (n < EE) g_hwh_h[(size_t)r*EE + n] = __float2half(v);
                    else        g_gate[(size_t)r*EE + (n-EE)] = sigfast(v);
                } else {
                    if (n < VSZ && g_dec[r] >= tt)
                        outp[(size_t)r*TCAP*VSZ + (size_t)tt*VSZ + n] = acc[mt][nt][q] + fc1b[n];
                }
            }
}

// ---------------- gstep: GRU GEMM (interleaved gates) + fused combine, split-K 8 ----------------
__global__ __launch_bounds__(256) void gstep(int t){
    __shared__ __align__(16) unsigned sb[8192];     // 32KB: As/Ws then reused as G tile
    unsigned (*As)[64][17]  = (unsigned(*)[64][17])sb;
    unsigned (*Ws)[128][17] = (unsigned(*)[128][17])(sb + 2*64*17);
    int tile = blockIdx.x;              // 0..15
    int n0 = tile*128;
    float acc[2][4][4];
    #pragma unroll
    for (int i=0;i<2;i++)
        #pragma unroll
        for (int j=0;j<4;j++)
            #pragma unroll
            for (int q=0;q<4;q++) acc[i][j][q]=0.f;
    int kb = blockIdx.z * (KCAT/8);
    mm_body(g_inp, KCAT, g_Wg + (size_t)n0*KCAT, 128, KCAT, kb, kb + KCAT/8, As, Ws, acc);
    if (!splitk_reduce(acc, tile, 8)) return;

    int tid = threadIdx.x;
    int w = tid >> 5, lane = tid & 31, g = lane >> 2, c = lane & 3;
    int wm = (w >> 2) * 32, wn = (w & 3) * 32;
    float* Gt = (float*)sb;             // [64][128]
    #pragma unroll
    for (int mt=0;mt<2;mt++)
        #pragma unroll
        for (int nt=0;nt<4;nt++)
            #pragma unroll
            for (int q=0;q<4;q++){
                int r  = wm + mt*16 + g + ((q>=2)?8:0);
                int cc = wn + nt*8 + 2*c + (q&1);
                Gt[r*128 + cc] = acc[mt][nt][q] + g_bg[n0 + cc];
            }
    __syncthreads();
    int jbase = n0 >> 2;
    for (int idx = tid; idx < 2048; idx += 256){
        int r  = idx >> 5;
        int jl = idx & 31;
        float G0 = Gt[r*128 + jl*4 + 0];
        float G1 = Gt[r*128 + jl*4 + 1];
        float G2 = Gt[r*128 + jl*4 + 2];
        float G3 = Gt[r*128 + jl*4 + 3];
        float rr = sigf(G0), zz = sigf(G1);
        float nn = tanhf(G2 + rr*G3);
        int j = jbase + jl;
        float h = g_h[r*HH + j];
        if (g_dec[r] >= t) g_h[r*HH + j] = (1.f - zz)*nn + zz*h;
    }
}

// ---------------- attention logits (fp16, tanh.approx.f16x2) ----------------
__global__ __launch_bounds__(256) void att_kernel(const float* __restrict__ Vw,
                                                  const float* __restrict__ Vb){
    int b = blockIdx.y, p0 = blockIdx.x*4;
    int tid = threadIdx.x;
    const uint4* xbase = (const uint4*)(g_xwx_h + (size_t)(b*PP + p0)*EE);
    uint4 hv = ((const uint4*)(g_hwh_h + (size_t)b*EE))[tid];
    float4 v0 = ((const float4*)Vw)[2*tid];
    float4 v1 = ((const float4*)Vw)[2*tid+1];
    float s[4];
    #pragma unroll
    for (int pp = 0; pp < 4; pp++){
        uint4 xv = xbase[(size_t)pp*(EE/8) + tid];
        unsigned t0 = tanh2(hadd2u(xv.x, hv.x));
        unsigned t1 = tanh2(hadd2u(xv.y, hv.y));
        unsigned t2 = tanh2(hadd2u(xv.z, hv.z));
        unsigned t3 = tanh2(hadd2u(xv.w, hv.w));
        float2 f0 = __half22float2(*(__half2*)&t0);
        float2 f1 = __half22float2(*(__half2*)&t1);
        float2 f2 = __half22float2(*(__half2*)&t2);
        float2 f3 = __half22float2(*(__half2*)&t3);
        float a = f0.x*v0.x + f0.y*v0.y;
        a = fmaf(f1.x, v0.z, a); a = fmaf(f1.y, v0.w, a);
        a = fmaf(f2.x, v1.x, a); a = fmaf(f2.y, v1.y, a);
        a = fmaf(f3.x, v1.z, a); a = fmaf(f3.y, v1.w, a);
        s[pp] = a;
    }
    #pragma unroll
    for (int pp = 0; pp < 4; pp++)
        #pragma unroll
        for (int o = 16; o > 0; o >>= 1) s[pp] += __shfl_xor_sync(0xffffffffu, s[pp], o);
    __shared__ float sh[4][8];
    if ((tid & 31) == 0)
        #pragma unroll
        for (int pp = 0; pp < 4; pp++) sh[pp][tid>>5] = s[pp];
    __syncthreads();
    if (tid < 4){
        float tt = 0.f;
        #pragma unroll
        for (int w2 = 0; w2 < 8; w2++) tt += sh[tid][w2];
        g_lam[b*PP + p0 + tid] = tt + Vb[0];
    }
}

// ---------------- zbuild: softmax + z (fp16 feats) + embed + h concat ----------------
__global__ __launch_bounds__(256) void zbuild_kernel(const int* __restrict__ caps,
                                                     const float* __restrict__ embw,
                                                     float* __restrict__ outp, int t){
    int b = blockIdx.y, tid = threadIdx.x, bx = blockIdx.x;
    if (bx >= 4){
        // embed + h concat (no softmax needed)
        int tok = caps[b*TCAP + t];
        if (bx == 4){
            g_inp[(size_t)b*KCAT + 2048 + tid]       = embw[(size_t)tok*EMBD + tid];
            g_inp[(size_t)b*KCAT + 2048 + 256 + tid] = embw[(size_t)tok*EMBD + 256 + tid];
        } else {
            g_inp[(size_t)b*KCAT + 2560 + tid]       = g_h[b*HH + tid];
            g_inp[(size_t)b*KCAT + 2560 + 256 + tid] = g_h[b*HH + 256 + tid];
        }
        return;
    }
    __shared__ float red[256];
    __shared__ float salpha[PP];
    float v = (tid < PP) ? g_lam[b*PP + tid] : -1e30f;
    red[tid] = v; __syncthreads();
    for (int s2 = 128; s2 > 0; s2 >>= 1){ if (tid < s2) red[tid] = fmaxf(red[tid], red[tid+s2]); __syncthreads(); }
    float mx = red[0]; __syncthreads();
    float e = (tid < PP) ? expf(v - mx) : 0.f;
    red[tid] = e; __syncthreads();
    for (int s2 = 128; s2 > 0; s2 >>= 1){ if (tid < s2) red[tid] += red[tid+s2]; __syncthreads(); }
    float inv = 1.f / red[0];
    if (tid < PP) salpha[tid] = e * inv;
    __syncthreads();
    if (bx == 0 && tid < PP && g_dec[b] >= t)
        outp[ALPHA_OFF + (size_t)b*TCAP*PP + (size_t)t*PP + tid] = salpha[tid];

    int c2 = bx*256 + tid;              // half2 column index, 0..1023
    const __half2* fb = (const __half2*)(g_feat_h + (size_t)b*PP*EE) + c2;
    float2 acc = make_float2(0.f, 0.f);
    #pragma unroll 4
    for (int p = 0; p < PP; p++){
        float2 f2 = __half22float2(fb[(size_t)p*(EE/2)]);
        float al = salpha[p];
        acc.x = fmaf(al, f2.x, acc.x);
        acc.y = fmaf(al, f2.y, acc.y);
    }
    int e0 = 2*c2;
    g_inp[(size_t)b*KCAT + e0]     = g_gate[b*EE + e0]     * acc.x;
    g_inp[(size_t)b*KCAT + e0 + 1] = g_gate[b*EE + e0 + 1] * acc.y;
}

// ---------------- launch ----------------
extern "C" void kernel_launch(void* const* d_in, const int* in_sizes, int n_in,
                              void* d_out, int out_size){
    const float* features = (const float*)d_in[0];
    const int*   captions = (const int*)  d_in[1];
    const int*   lengths  = (const int*)  d_in[2];
    const float* Wx_w  = (const float*)d_in[3];
    const float* Wx_b  = (const float*)d_in[4];
    const float* Wh_w  = (const float*)d_in[5];
    const float* Wh_b  = (const float*)d_in[6];
    const float* V_w   = (const float*)d_in[7];
    const float* V_b   = (const float*)d_in[8];
    const float* ih_w  = (const float*)d_in[9];
    const float* ih_b  = (const float*)d_in[10];
    const float* fb_w  = (const float*)d_in[11];
    const float* fb_b  = (const float*)d_in[12];
    const float* emb_w = (const float*)d_in[13];
    const float* gih_w = (const float*)d_in[14];
    const float* gih_b = (const float*)d_in[15];
    const float* ghh_w = (const float*)d_in[16];
    const float* ghh_b = (const float*)d_in[17];
    const float* fc1_w = (const float*)d_in[18];
    const float* fc1_b = (const float*)d_in[19];
    float* out = (float*)d_out;

    cudaMemsetAsync(d_out, 0, (size_t)out_size * sizeof(float), 0);
    dec_kernel<<<1, 64>>>(lengths, out);
    mean_kernel<<<dim3(EE/256, BB), 256>>>(features);
    feat2h<<<(int)(((size_t)BPP*EE/2)/256), 256>>>(features);
    build_wcomb<<<(4096*512)/256, 256>>>(Wh_w, Wh_b, fb_w, fb_b);
    build_wg<<<(int)(((size_t)2048*KCAT)/256), 256>>>(gih_w, gih_b, ghh_w, ghh_b);
    h0_kernel<<<4096, 256>>>(ih_w, ih_b);
    xwx_tc<<<dim3(EE/128, BPP/128), 256>>>(features, Wx_w, Wx_b);

    for (int t = 0; t < TMAXX; t++){
        wstep<<<dim3(111, 1, 2), 256>>>(fc1_w, fc1_b, out, t);   // hwh/gate(t) + fc1(t-1)
        att_kernel<<<dim3(PP/4, BB), 256>>>(V_w, V_b);
        zbuild_kernel<<<dim3(6, BB), 256>>>(captions, emb_w, out, t);
        gstep<<<dim3(16, 1, 8), 256>>>(t);                        // GRU GEMM + combine
    }
    wstep<<<dim3(111, 1, 2), 256>>>(fc1_w, fc1_b, out, TMAXX);    // final fc1(48)
}

// round 13
// speedup vs baseline: 3.0171x; 1.0036x over previous
#include <cuda_runtime.h>
#include <cuda_fp16.h>
#include <math.h>

#define BB    64
#define PP    196
#define EE    2048
#define HH    512
#define EMBD  512
#define VSZ   10000
#define TCAP  50
#define TMAXX 49
#define BPP   (BB*PP)
#define KIH   (EE+EMBD)       // 2560
#define KCAT  3072            // EE+EMBD+HH

#define PRED_SZ   ((size_t)BB*TCAP*VSZ)
#define ALPHA_OFF PRED_SZ
#define ALPHA_SZ  ((size_t)BB*TCAP*PP)
#define DEC_OFF   (ALPHA_OFF + ALPHA_SZ)

// ---------------- scratch ----------------
__device__ __half g_xwx_h[(size_t)BPP*EE];     // fp16 attention projections
__device__ __half g_feat_h[(size_t)BPP*EE];    // fp16 features copy
__device__ __half g_hwh_h[BB*EE];
__device__ float g_fm  [BB*EE];
__device__ float g_h   [BB*HH];
__device__ float g_gate[BB*EE];
__device__ float g_lam [BB*PP];
__device__ float g_inp [BB*KCAT];
__device__ int   g_dec [BB];
__device__ float g_part[(size_t)111*8*8192];
__device__ unsigned g_cnt[128];                // zero-init; finisher resets
__device__ float g_Wcomb[4096*512];            // [Wh_w ; f_beta_w]
__device__ float g_bcomb[4096];
__device__ float g_Wg[(size_t)2048*KCAT];      // gate-interleaved GRU weight
__device__ float g_bg[2048];

// ---------------- helpers ----------------
__device__ __forceinline__ unsigned tf32c(float x){
    unsigned r; asm("cvt.rna.tf32.f32 %0, %1;" : "=r"(r) : "f"(x)); return r;
}
__device__ __forceinline__ void mma8(float* c, unsigned a0,unsigned a1,unsigned a2,unsigned a3,
                                     unsigned b0,unsigned b1){
    asm volatile("mma.sync.aligned.m16n8k8.row.col.f32.tf32.tf32.f32 "
        "{%0,%1,%2,%3}, {%4,%5,%6,%7}, {%8,%9}, {%0,%1,%2,%3};"
        : "+f"(c[0]),"+f"(c[1]),"+f"(c[2]),"+f"(c[3])
        : "r"(a0),"r"(a1),"r"(a2),"r"(a3),"r"(b0),"r"(b1));
}
__device__ __forceinline__ unsigned hadd2u(unsigned a, unsigned b){
    unsigned r; asm("add.f16x2 %0,%1,%2;" : "=r"(r) : "r"(a), "r"(b)); return r;
}
__device__ __forceinline__ unsigned tanh2(unsigned x){
    unsigned r; asm("tanh.approx.f16x2 %0,%1;" : "=r"(r) : "r"(x)); return r;
}
__device__ __forceinline__ void cpa16(void* smem, const void* g){
    unsigned sa = (unsigned)__cvta_generic_to_shared(smem);
    asm volatile("cp.async.cg.shared.global [%0], [%1], 16;" :: "r"(sa), "l"(g));
}
__device__ __forceinline__ void cpcommit(){ asm volatile("cp.async.commit_group;"); }
__device__ __forceinline__ void cpwait1(){ asm volatile("cp.async.wait_group 1;"); }
__device__ __forceinline__ float sigf(float x){ return 1.f/(1.f+expf(-x)); }
__device__ __forceinline__ float sigfast(float x){ return 1.f/(1.f+__expf(-x)); }

// ---------------- preamble ----------------
__global__ void dec_kernel(const int* __restrict__ lengths, float* __restrict__ outp){
    int b = threadIdx.x;
    if (b < BB){ int d = lengths[b]-1; g_dec[b] = d; outp[DEC_OFF+b] = (float)d; }
}

__global__ __launch_bounds__(256) void mean_kernel(const float* __restrict__ feat){
    int b = blockIdx.y;
    int e = blockIdx.x*256 + threadIdx.x;
    const float* f = feat + (size_t)b*PP*EE + e;
    float s = 0.f;
    #pragma unroll 4
    for (int p = 0; p < PP; p++) s += f[(size_t)p*EE];
    g_fm[b*EE+e] = s * (1.f/(float)PP);
}

__global__ __launch_bounds__(256) void feat2h(const float* __restrict__ f){
    size_t i = (size_t)blockIdx.x*256 + threadIdx.x;   // over BPP*EE/2 half2
    float2 v = ((const float2*)f)[i];
    ((__half2*)g_feat_h)[i] = __floats2half2_rn(v.x, v.y);
}

__global__ __launch_bounds__(256) void build_wcomb(const float* __restrict__ Whw, const float* __restrict__ Whb,
                                                   const float* __restrict__ fbw, const float* __restrict__ fbb){
    int idx = blockIdx.x*256 + threadIdx.x;      // 4096*512
    int n = idx >> 9, k = idx & 511;
    g_Wcomb[idx] = (n < EE) ? Whw[n*HH+k] : fbw[(n-EE)*HH+k];
    if (k == 0) g_bcomb[n] = (n < EE) ? Whb[n] : fbb[n-EE];
}

// gate-interleaved GRU weight: new row m = j*4+q, q in {r,z,n,hn}
__global__ __launch_bounds__(256) void build_wg(const float* __restrict__ gihw, const float* __restrict__ gihb,
                                                const float* __restrict__ ghhw, const float* __restrict__ ghhb){
    size_t idx = (size_t)blockIdx.x*256 + threadIdx.x;    // 2048*3072
    int m = (int)(idx / KCAT), k = (int)(idx % KCAT);
    int j = m >> 2, q = m & 3;
    int n = q*512 + j;         // old row in [0,2048)
    float v;
    if (n < 1024)       v = (k < KIH) ? gihw[(size_t)n*KIH+k] : ghhw[(size_t)n*HH + (k-KIH)];
    else if (n < 1536)  v = (k < KIH) ? gihw[(size_t)n*KIH+k] : 0.f;
    else                v = (k < KIH) ? 0.f : ghhw[(size_t)(n-512)*HH + (k-KIH)];
    g_Wg[idx] = v;
    if (k == 0){
        float bb;
        if (n < 1024)      bb = gihb[n] + ghhb[n];
        else if (n < 1536) bb = gihb[n];
        else               bb = ghhb[n-512];
        g_bg[m] = bb;
    }
}

// h0: precise fp32 dot, one warp per output
__global__ __launch_bounds__(256) void h0_kernel(const float* __restrict__ W,
                                                 const float* __restrict__ bv){
    int gw = blockIdx.x*8 + (threadIdx.x >> 5);
    int lane = threadIdx.x & 31;
    int b = gw >> 9, n = gw & 511;
    const float* a = g_fm + (size_t)b*EE;
    const float* w = W + (size_t)n*EE;
    float s = 0.f;
    #pragma unroll 4
    for (int k = lane; k < EE; k += 32) s = fmaf(a[k], w[k], s);
    #pragma unroll
    for (int o = 16; o > 0; o >>= 1) s += __shfl_xor_sync(0xffffffffu, s, o);
    if (lane == 0) g_h[b*HH + n] = s + bv[n];
}

// ---------------- xwx: tf32 cp.async double-buffered GEMM -> fp16 ----------------
#define XS 20
__global__ __launch_bounds__(256) void xwx_tc(const float* __restrict__ A,
                                              const float* __restrict__ W,
                                              const float* __restrict__ bias){
    __shared__ float As[2][128*XS];
    __shared__ float Bs[2][128*XS];
    int tid = threadIdx.x;
    int m0 = blockIdx.y*128, n0 = blockIdx.x*128;
    int rc = tid >> 2, kc = (tid & 3) * 4;
    const float* Ap = A + (size_t)(m0+rc)*EE + kc;
    const float* Wp = W + (size_t)(n0+rc)*EE + kc;
    int wq = tid >> 5, lane = tid & 31, g = lane >> 2, ct = lane & 3;
    int wm = (wq >> 2) * 64, wn = (wq & 3) * 32;
    float acc[4][4][4];
    #pragma unroll
    for (int i=0;i<4;i++)
        #pragma unroll
        for (int j=0;j<4;j++)
            #pragma unroll
            for (int q=0;q<4;q++) acc[i][j][q] = 0.f;
    #pragma unroll
    for (int s = 0; s < 2; s++){
        int k0 = s*16;
        cpa16(&As[s][rc*XS + kc],      Ap + k0);
        cpa16(&As[s][(rc+64)*XS + kc], Ap + (size_t)64*EE + k0);
        cpa16(&Bs[s][rc*XS + kc],      Wp + k0);
        cpa16(&Bs[s][(rc+64)*XS + kc], Wp + (size_t)64*EE + k0);
        cpcommit();
    }
    for (int k0 = 0; k0 < EE; k0 += 16){
        int s = (k0 >> 4) & 1;
        cpwait1();
        __syncthreads();
        const unsigned* Au = (const unsigned*)As[s];
        const unsigned* Bu = (const unsigned*)Bs[s];
        #pragma unroll
        for (int kq = 0; kq < 2; kq++){
            int k8 = kq*8;
            unsigned ah[4][4], bh[4][2];
            #pragma unroll
            for (int mt=0;mt<4;mt++){
                int rm = wm + mt*16;
                ah[mt][0] = Au[(rm+g  )*XS + k8+ct];
                ah[mt][1] = Au[(rm+g+8)*XS + k8+ct];
                ah[mt][2] = Au[(rm+g  )*XS + k8+ct+4];
                ah[mt][3] = Au[(rm+g+8)*XS + k8+ct+4];
            }
            #pragma unroll
            for (int nt=0;nt<4;nt++){
                int nb = wn + nt*8;
                bh[nt][0] = Bu[(nb+g)*XS + k8+ct];
                bh[nt][1] = Bu[(nb+g)*XS + k8+ct+4];
            }
            #pragma unroll
            for (int mt=0;mt<4;mt++)
                #pragma unroll
                for (int nt=0;nt<4;nt++)
                    mma8(acc[mt][nt], ah[mt][0],ah[mt][1],ah[mt][2],ah[mt][3], bh[nt][0],bh[nt][1]);
        }
        __syncthreads();
        if (k0 + 32 < EE){
            int kn = k0 + 32;
            cpa16(&As[s][rc*XS + kc],      Ap + kn);
            cpa16(&As[s][(rc+64)*XS + kc], Ap + (size_t)64*EE + kn);
            cpa16(&Bs[s][rc*XS + kc],      Wp + kn);
            cpa16(&Bs[s][(rc+64)*XS + kc], Wp + (size_t)64*EE + kn);
            cpcommit();
        }
    }
    #pragma unroll
    for (int mt=0;mt<4;mt++)
        #pragma unroll
        for (int nt=0;nt<4;nt++){
            int cn = n0 + wn + nt*8 + 2*ct;
            float b0 = bias[cn], b1 = bias[cn+1];
            size_t r1 = (size_t)(m0 + wm + mt*16 + g);
            *(__half2*)&g_xwx_h[r1*EE + cn]     = __floats2half2_rn(acc[mt][nt][0]+b0, acc[mt][nt][1]+b1);
            *(__half2*)&g_xwx_h[(r1+8)*EE + cn] = __floats2half2_rn(acc[mt][nt][2]+b0, acc[mt][nt][3]+b1);
        }
}

// ---------------- shared 64x128 compensated-tf32 tile body ----------------
__device__ __forceinline__ void mm_body(const float* __restrict__ A, int lda,
                                        const float* __restrict__ W0, int wrows, int K,
                                        int kbeg, int kend,
                                        unsigned (*As)[64][17], unsigned (*Ws)[128][17],
                                        float acc[2][4][4]){
    int tid = threadIdx.x;
    int arow = tid >> 2, acol = (tid & 3) * 4;
    int brow = tid >> 1, bcol = (tid & 1) * 8;
    bool bok = brow < wrows;
    const float* Ap = A + (size_t)arow*lda + acol;
    const float* Wp = W0 + (size_t)brow*K + bcol;
    int w = tid >> 5, lane = tid & 31, g = lane >> 2, c = lane & 3;
    int wm = (w >> 2) * 32, wn = (w & 3) * 32;
    float4 ra = *(const float4*)(Ap + kbeg);
    float4 rb0 = make_float4(0,0,0,0), rb1 = rb0;
    if (bok){ rb0 = *(const float4*)(Wp + kbeg); rb1 = *(const float4*)(Wp + kbeg + 4); }
    for (int k0 = kbeg; k0 < kend; k0 += 16){
        float av[4] = {ra.x,ra.y,ra.z,ra.w};
        #pragma unroll
        for (int j=0;j<4;j++){
            unsigned hi = tf32c(av[j]);
            As[0][arow][acol+j] = hi;
            As[1][arow][acol+j] = tf32c(av[j] - __uint_as_float(hi));
        }
        float bvv[8] = {rb0.x,rb0.y,rb0.z,rb0.w, rb1.x,rb1.y,rb1.z,rb1.w};
        #pragma unroll
        for (int j=0;j<8;j++){
            unsigned hi = tf32c(bvv[j]);
            Ws[0][brow][bcol+j] = hi;
            Ws[1][brow][bcol+j] = tf32c(bvv[j] - __uint_as_float(hi));
        }
        __syncthreads();
        if (k0 + 16 < kend){
            ra = *(const float4*)(Ap + k0 + 16);
            if (bok){ rb0 = *(const float4*)(Wp + k0 + 16); rb1 = *(const float4*)(Wp + k0 + 20); }
        }
        #pragma unroll
        for (int kq = 0; kq < 2; kq++){
            int k8 = kq*8;
            unsigned ah[2][4], al[2][4], bh[4][2], bl[4][2];
            #pragma unroll
            for (int mt=0;mt<2;mt++){
                int rm = wm + mt*16;
                ah[mt][0]=As[0][rm+g][k8+c];   ah[mt][1]=As[0][rm+g+8][k8+c];
                ah[mt][2]=As[0][rm+g][k8+c+4]; ah[mt][3]=As[0][rm+g+8][k8+c+4];
                al[mt][0]=As[1][rm+g][k8+c];   al[mt][1]=As[1][rm+g+8][k8+c];
                al[mt][2]=As[1][rm+g][k8+c+4]; al[mt][3]=As[1][rm+g+8][k8+c+4];
            }
            #pragma unroll
            for (int nt=0;nt<4;nt++){
                int nb = wn + nt*8;
                bh[nt][0]=Ws[0][nb+g][k8+c]; bh[nt][1]=Ws[0][nb+g][k8+c+4];
                bl[nt][0]=Ws[1][nb+g][k8+c]; bl[nt][1]=Ws[1][nb+g][k8+c+4];
            }
            #pragma unroll
            for (int mt=0;mt<2;mt++)
                #pragma unroll
                for (int nt=0;nt<4;nt++){
                    mma8(acc[mt][nt], ah[mt][0],ah[mt][1],ah[mt][2],ah[mt][3], bh[nt][0],bh[nt][1]);
                    mma8(acc[mt][nt], al[mt][0],al[mt][1],al[mt][2],al[mt][3], bh[nt][0],bh[nt][1]);
                    mma8(acc[mt][nt], ah[mt][0],ah[mt][1],ah[mt][2],ah[mt][3], bl[nt][0],bl[nt][1]);
                }
        }
        __syncthreads();
    }
}

__device__ bool splitk_reduce(float acc[2][4][4], int slot, int ksplit){
    __shared__ unsigned s_last;
    int tid = threadIdx.x;
    int w = tid >> 5, lane = tid & 31, g = lane >> 2, c = lane & 3;
    int wm = (w >> 2) * 32, wn = (w & 3) * 32;
    float* pp = &g_part[((size_t)slot*8 + blockIdx.z)*8192];
    #pragma unroll
    for (int mt=0;mt<2;mt++)
        #pragma unroll
        for (int nt=0;nt<4;nt++){
            int r1 = wm + mt*16 + g;
            int cc = wn + nt*8 + 2*c;
            pp[r1*128 + cc]       = acc[mt][nt][0];
            pp[r1*128 + cc+1]     = acc[mt][nt][1];
            pp[(r1+8)*128 + cc]   = acc[mt][nt][2];
            pp[(r1+8)*128 + cc+1] = acc[mt][nt][3];
        }
    __threadfence();
    __syncthreads();
    if (tid == 0)
        s_last = (atomicAdd(&g_cnt[slot], 1u) == (unsigned)(ksplit-1)) ? 1u : 0u;
    __syncthreads();
    if (!s_last) return false;
    __threadfence();
    #pragma unroll
    for (int mt=0;mt<2;mt++)
        #pragma unroll
        for (int nt=0;nt<4;nt++){
            int r1 = wm + mt*16 + g;
            int cc = wn + nt*8 + 2*c;
            float s0=0.f,s1=0.f,s2=0.f,s3=0.f;
            for (int kz = 0; kz < ksplit; kz++){
                const float* q = &g_part[((size_t)slot*8 + kz)*8192];
                s0 += q[r1*128 + cc];     s1 += q[r1*128 + cc+1];
                s2 += q[(r1+8)*128 + cc]; s3 += q[(r1+8)*128 + cc+1];
            }
            acc[mt][nt][0]=s0; acc[mt][nt][1]=s1; acc[mt][nt][2]=s2; acc[mt][nt][3]=s3;
        }
    __syncthreads();
    if (tid == 0) g_cnt[slot] = 0;
    return true;
}

// ---------------- wstep: hwh/gate(t) + fc1(t-1), split-K 2 ----------------
__global__ __launch_bounds__(256) void wstep(const float* __restrict__ fc1w,
                                             const float* __restrict__ fc1b,
                                             float* __restrict__ outp, int t){
    int tile = blockIdx.x;              // 0..110
    bool isC = tile < 32;
    if (isC  && t == TMAXX) return;
    if (!isC && t == 0)     return;
    __shared__ unsigned As[2][64][17];
    __shared__ unsigned Ws[2][128][17];
    int n0 = isC ? tile*128 : (tile-32)*128;
    const float* W = isC ? (g_Wcomb + (size_t)n0*HH) : (fc1w + (size_t)n0*HH);
    int wrows = isC ? 128 : (VSZ - n0 < 128 ? VSZ - n0 : 128);
    float acc[2][4][4];
    #pragma unroll
    for (int i=0;i<2;i++)
        #pragma unroll
        for (int j=0;j<4;j++)
            #pragma unroll
            for (int q=0;q<4;q++) acc[i][j][q]=0.f;
    int kb = blockIdx.z * (HH/2);
    mm_body(g_h, HH, W, wrows, HH, kb, kb + HH/2, As, Ws, acc);
    if (!splitk_reduce(acc, tile, 2)) return;

    int tid = threadIdx.x;
    int w = tid >> 5, lane = tid & 31, g = lane >> 2, c = lane & 3;
    int wm = (w >> 2) * 32, wn = (w & 3) * 32;
    int tt = t - 1;
    #pragma unroll
    for (int mt=0;mt<2;mt++)
        #pragma unroll
        for (int nt=0;nt<4;nt++)
            #pragma unroll
            for (int q=0;q<4;q++){
                int r = wm + mt*16 + g + ((q>=2)?8:0);
                int n = n0 + wn + nt*8 + 2*c + (q&1);
                if (isC){
                    float v = acc[mt][nt][q] + g_bcomb[n];
                    if (n < EE) g_hwh_h[(size_t)r*EE + n] = __float2half(v);
                    else        g_gate[(size_t)r*EE + (n-EE)] = sigfast(v);
                } else {
                    if (n < VSZ && g_dec[r] >= tt)
                        outp[(size_t)r*TCAP*VSZ + (size_t)tt*VSZ + n] = acc[mt][nt][q] + fc1b[n];
                }
            }
}

// ---------------- gstep: GRU GEMM (interleaved gates) + fused combine, split-K 8 ----------------
__global__ __launch_bounds__(256) void gstep(int t){
    __shared__ __align__(16) unsigned sb[8192];     // 32KB: As/Ws then reused as G tile
    unsigned (*As)[64][17]  = (unsigned(*)[64][17])sb;
    unsigned (*Ws)[128][17] = (unsigned(*)[128][17])(sb + 2*64*17);
    int tile = blockIdx.x;              // 0..15
    int n0 = tile*128;
    float acc[2][4][4];
    #pragma unroll
    for (int i=0;i<2;i++)
        #pragma unroll
        for (int j=0;j<4;j++)
            #pragma unroll
            for (int q=0;q<4;q++) acc[i][j][q]=0.f;
    int kb = blockIdx.z * (KCAT/8);
    mm_body(g_inp, KCAT, g_Wg + (size_t)n0*KCAT, 128, KCAT, kb, kb + KCAT/8, As, Ws, acc);
    if (!splitk_reduce(acc, tile, 8)) return;

    int tid = threadIdx.x;
    int w = tid >> 5, lane = tid & 31, g = lane >> 2, c = lane & 3;
    int wm = (w >> 2) * 32, wn = (w & 3) * 32;
    float* Gt = (float*)sb;             // [64][128]
    #pragma unroll
    for (int mt=0;mt<2;mt++)
        #pragma unroll
        for (int nt=0;nt<4;nt++)
            #pragma unroll
            for (int q=0;q<4;q++){
                int r  = wm + mt*16 + g + ((q>=2)?8:0);
                int cc = wn + nt*8 + 2*c + (q&1);
                Gt[r*128 + cc] = acc[mt][nt][q] + g_bg[n0 + cc];
            }
    __syncthreads();
    int jbase = n0 >> 2;
    for (int idx = tid; idx < 2048; idx += 256){
        int r  = idx >> 5;
        int jl = idx & 31;
        float G0 = Gt[r*128 + jl*4 + 0];
        float G1 = Gt[r*128 + jl*4 + 1];
        float G2 = Gt[r*128 + jl*4 + 2];
        float G3 = Gt[r*128 + jl*4 + 3];
        float rr = sigf(G0), zz = sigf(G1);
        float nn = tanhf(G2 + rr*G3);
        int j = jbase + jl;
        float h = g_h[r*HH + j];
        if (g_dec[r] >= t) g_h[r*HH + j] = (1.f - zz)*nn + zz*h;
    }
}

// ---------------- attention logits (fp16, tanh.approx.f16x2) ----------------
__global__ __launch_bounds__(256) void att_kernel(const float* __restrict__ Vw,
                                                  const float* __restrict__ Vb){
    int b = blockIdx.y, p0 = blockIdx.x*4;
    int tid = threadIdx.x;
    const uint4* xbase = (const uint4*)(g_xwx_h + (size_t)(b*PP + p0)*EE);
    uint4 hv = ((const uint4*)(g_hwh_h + (size_t)b*EE))[tid];
    float4 v0 = ((const float4*)Vw)[2*tid];
    float4 v1 = ((const float4*)Vw)[2*tid+1];
    float s[4];
    #pragma unroll
    for (int pp = 0; pp < 4; pp++){
        uint4 xv = xbase[(size_t)pp*(EE/8) + tid];
        unsigned t0 = tanh2(hadd2u(xv.x, hv.x));
        unsigned t1 = tanh2(hadd2u(xv.y, hv.y));
        unsigned t2 = tanh2(hadd2u(xv.z, hv.z));
        unsigned t3 = tanh2(hadd2u(xv.w, hv.w));
        float2 f0 = __half22float2(*(__half2*)&t0);
        float2 f1 = __half22float2(*(__half2*)&t1);
        float2 f2 = __half22float2(*(__half2*)&t2);
        float2 f3 = __half22float2(*(__half2*)&t3);
        float a = f0.x*v0.x + f0.y*v0.y;
        a = fmaf(f1.x, v0.z, a); a = fmaf(f1.y, v0.w, a);
        a = fmaf(f2.x, v1.x, a); a = fmaf(f2.y, v1.y, a);
        a = fmaf(f3.x, v1.z, a); a = fmaf(f3.y, v1.w, a);
        s[pp] = a;
    }
    #pragma unroll
    for (int pp = 0; pp < 4; pp++)
        #pragma unroll
        for (int o = 16; o > 0; o >>= 1) s[pp] += __shfl_xor_sync(0xffffffffu, s[pp], o);
    __shared__ float sh[4][8];
    if ((tid & 31) == 0)
        #pragma unroll
        for (int pp = 0; pp < 4; pp++) sh[pp][tid>>5] = s[pp];
    __syncthreads();
    if (tid < 4){
        float tt = 0.f;
        #pragma unroll
        for (int w2 = 0; w2 < 8; w2++) tt += sh[tid][w2];
        g_lam[b*PP + p0 + tid] = tt + Vb[0];
    }
}

// ---------------- zbuild: softmax + z (fp16 feats) + embed + h concat ----------------
__global__ __launch_bounds__(256) void zbuild_kernel(const int* __restrict__ caps,
                                                     const float* __restrict__ embw,
                                                     float* __restrict__ outp, int t){
    int b = blockIdx.y, tid = threadIdx.x, bx = blockIdx.x;
    if (bx >= 4){
        // embed + h concat (no softmax needed)
        int tok = caps[b*TCAP + t];
        if (bx == 4){
            g_inp[(size_t)b*KCAT + 2048 + tid]       = embw[(size_t)tok*EMBD + tid];
            g_inp[(size_t)b*KCAT + 2048 + 256 + tid] = embw[(size_t)tok*EMBD + 256 + tid];
        } else {
            g_inp[(size_t)b*KCAT + 2560 + tid]       = g_h[b*HH + tid];
            g_inp[(size_t)b*KCAT + 2560 + 256 + tid] = g_h[b*HH + 256 + tid];
        }
        return;
    }
    __shared__ float red[256];
    __shared__ float salpha[PP];
    float v = (tid < PP) ? g_lam[b*PP + tid] : -1e30f;
    red[tid] = v; __syncthreads();
    for (int s2 = 128; s2 > 0; s2 >>= 1){ if (tid < s2) red[tid] = fmaxf(red[tid], red[tid+s2]); __syncthreads(); }
    float mx = red[0]; __syncthreads();
    float e = (tid < PP) ? expf(v - mx) : 0.f;
    red[tid] = e; __syncthreads();
    for (int s2 = 128; s2 > 0; s2 >>= 1){ if (tid < s2) red[tid] += red[tid+s2]; __syncthreads(); }
    float inv = 1.f / red[0];
    if (tid < PP) salpha[tid] = e * inv;
    __syncthreads();
    if (bx == 0 && tid < PP && g_dec[b] >= t)
        outp[ALPHA_OFF + (size_t)b*TCAP*PP + (size_t)t*PP + tid] = salpha[tid];

    int c2 = bx*256 + tid;              // half2 column index, 0..1023
    const __half2* fb = (const __half2*)(g_feat_h + (size_t)b*PP*EE) + c2;
    float2 acc = make_float2(0.f, 0.f);
    #pragma unroll 4
    for (int p = 0; p < PP; p++){
        float2 f2 = __half22float2(fb[(size_t)p*(EE/2)]);
        float al = salpha[p];
        acc.x = fmaf(al, f2.x, acc.x);
        acc.y = fmaf(al, f2.y, acc.y);
    }
    int e0 = 2*c2;
    g_inp[(size_t)b*KCAT + e0]     = g_gate[b*EE + e0]     * acc.x;
    g_inp[(size_t)b*KCAT + e0 + 1] = g_gate[b*EE + e0 + 1] * acc.y;
}

// ---------------- launch ----------------
extern "C" void kernel_launch(void* const* d_in, const int* in_sizes, int n_in,
                              void* d_out, int out_size){
    const float* features = (const float*)d_in[0];
    const int*   captions = (const int*)  d_in[1];
    const int*   lengths  = (const int*)  d_in[2];
    const float* Wx_w  = (const float*)d_in[3];
    const float* Wx_b  = (const float*)d_in[4];
    const float* Wh_w  = (const float*)d_in[5];
    const float* Wh_b  = (const float*)d_in[6];
    const float* V_w   = (const float*)d_in[7];
    const float* V_b   = (const float*)d_in[8];
    const float* ih_w  = (const float*)d_in[9];
    const float* ih_b  = (const float*)d_in[10];
    const float* fb_w  = (const float*)d_in[11];
    const float* fb_b  = (const float*)d_in[12];
    const float* emb_w = (const float*)d_in[13];
    const float* gih_w = (const float*)d_in[14];
    const float* gih_b = (const float*)d_in[15];
    const float* ghh_w = (const float*)d_in[16];
    const float* ghh_b = (const float*)d_in[17];
    const float* fc1_w = (const float*)d_in[18];
    const float* fc1_b = (const float*)d_in[19];
    float* out = (float*)d_out;

    cudaMemsetAsync(d_out, 0, (size_t)out_size * sizeof(float), 0);
    dec_kernel<<<1, 64>>>(lengths, out);
    mean_kernel<<<dim3(EE/256, BB), 256>>>(features);
    feat2h<<<(int)(((size_t)BPP*EE/2)/256), 256>>>(features);
    build_wcomb<<<(4096*512)/256, 256>>>(Wh_w, Wh_b, fb_w, fb_b);
    build_wg<<<(int)(((size_t)2048*KCAT)/256), 256>>>(gih_w, gih_b, ghh_w, ghh_b);
    h0_kernel<<<4096, 256>>>(ih_w, ih_b);
    xwx_tc<<<dim3(EE/128, BPP/128), 256>>>(features, Wx_w, Wx_b);

    for (int t = 0; t < TMAXX; t++){
        wstep<<<dim3(111, 1, 2), 256>>>(fc1_w, fc1_b, out, t);   // hwh/gate(t) + fc1(t-1)
        att_kernel<<<dim3(PP/4, BB), 256>>>(V_w, V_b);
        zbuild_kernel<<<dim3(6, BB), 256>>>(captions, emb_w, out, t);
        gstep<<<dim3(16, 1, 8), 256>>>(t);                        // GRU GEMM + combine
    }
    wstep<<<dim3(111, 1, 2), 256>>>(fc1_w, fc1_b, out, TMAXX);    // final fc1(48)
}